// round 12
// baseline (speedup 1.0000x reference)
#include <cuda_runtime.h>
#include <cuda_bf16.h>
#include <mma.h>
#include <math.h>
#include <stdint.h>

using namespace nvcuda;

#define N_NODES 100000
#define IN_CH   128
#define HIDDEN  128
#define OUT_CH  64
#define N_POS   600000
#define N_EDGES_TOT 1200000

#define SCAN_B 512
#define NB ((N_NODES + SCAN_B - 1) / SCAN_B)   // 196

// ---------------- scratch (no cudaMalloc allowed) ----------------
__device__ float g_h1[(size_t)N_NODES * HIDDEN];   // x @ W1
__device__ float g_h2[(size_t)N_NODES * OUT_CH];   // z1 @ W2
__device__ float g_z2[(size_t)N_NODES * OUT_CH];   // agg2 + b2
__device__ float g_dinv[N_NODES];
__device__ int   g_cnt[N_NODES];
__device__ int   g_cur[N_NODES];
__device__ int   g_offs[N_NODES + 1];
__device__ int   g_esrc[N_POS];
__device__ int   g_bsum[NB];
// bf16 hi/lo planes
__device__ __nv_bfloat16 gXh[(size_t)N_NODES * 128], gXl[(size_t)N_NODES * 128];
__device__ __nv_bfloat16 gZ1h[(size_t)N_NODES * 128], gZ1l[(size_t)N_NODES * 128];
__device__ __nv_bfloat16 gW1h[128 * 128], gW1l[128 * 128];
__device__ __nv_bfloat16 gW2h[128 * 64],  gW2l[128 * 64];

// ---------------- helpers ----------------
__device__ __forceinline__ uint32_t pack2(float a, float b) {
    uint32_t r;
    asm("cvt.rn.satfinite.bf16x2.f32 %0, %1, %2;" : "=r"(r) : "f"(b), "f"(a));
    return r;
}
__device__ __forceinline__ float bf16_round(float v) {
    return __bfloat162float(__float2bfloat16(v));
}
__device__ __forceinline__ void cvt4(float4 v, uint2& h, uint2& l) {
    h = make_uint2(pack2(v.x, v.y), pack2(v.z, v.w));
    l = make_uint2(pack2(v.x - bf16_round(v.x), v.y - bf16_round(v.y)),
                   pack2(v.z - bf16_round(v.z), v.w - bf16_round(v.w)));
}

// ---------------- convert x/W1/W2 to bf16 hi/lo planes; zero counters ----------------
__global__ void k_cvt(const float* __restrict__ x,
                      const float* __restrict__ W1,
                      const float* __restrict__ W2) {
    int i = blockIdx.x * blockDim.x + threadIdx.x;   // float4 group index
    if (i < N_NODES) { g_cnt[i] = 0; g_cur[i] = 0; }
    if (i < (N_NODES * 128) / 4) {
        float4 v = ((const float4*)x)[i];
        uint2 h, l; cvt4(v, h, l);
        ((uint2*)gXh)[i] = h;
        ((uint2*)gXl)[i] = l;
    }
    if (i < (128 * 128) / 4) {
        float4 v = ((const float4*)W1)[i];
        uint2 h, l; cvt4(v, h, l);
        ((uint2*)gW1h)[i] = h;
        ((uint2*)gW1l)[i] = l;
    }
    if (i < (128 * 64) / 4) {
        float4 v = ((const float4*)W2)[i];
        uint2 h, l; cvt4(v, h, l);
        ((uint2*)gW2h)[i] = h;
        ((uint2*)gW2l)[i] = l;
    }
}

__global__ void k_hist(const int* __restrict__ pos_ei) {
    int e = blockIdx.x * blockDim.x + threadIdx.x;
    if (e < N_POS) {
        int d = pos_ei[N_POS + e];
        atomicAdd(&g_cnt[d], 1);
    }
}

__global__ __launch_bounds__(SCAN_B) void k_scanA() {
    __shared__ int wsum[16];
    int i = blockIdx.x * SCAN_B + threadIdx.x;
    int lane = threadIdx.x & 31, wid = threadIdx.x >> 5;
    int v = (i < N_NODES) ? g_cnt[i] : 0;
    if (i < N_NODES) g_dinv[i] = rsqrtf((float)v + 1.0f);

    int s = v;
    #pragma unroll
    for (int o = 1; o < 32; o <<= 1) {
        int t = __shfl_up_sync(0xffffffffu, s, o);
        if (lane >= o) s += t;
    }
    if (lane == 31) wsum[wid] = s;
    __syncthreads();
    if (wid == 0) {
        int w = (lane < 16) ? wsum[lane] : 0;
        #pragma unroll
        for (int o = 1; o < 16; o <<= 1) {
            int t = __shfl_up_sync(0xffffffffu, w, o);
            if (lane >= o) w += t;
        }
        if (lane < 16) wsum[lane] = w;
    }
    __syncthreads();
    int excl = s - v + (wid > 0 ? wsum[wid - 1] : 0);
    if (i < N_NODES) g_offs[i] = excl;
    if (threadIdx.x == 0) g_bsum[blockIdx.x] = wsum[15];
}

__global__ __launch_bounds__(256) void k_scanB() {
    __shared__ int wsum[8];
    int lane = threadIdx.x & 31, wid = threadIdx.x >> 5;
    int v = (threadIdx.x < NB) ? g_bsum[threadIdx.x] : 0;
    int s = v;
    #pragma unroll
    for (int o = 1; o < 32; o <<= 1) {
        int t = __shfl_up_sync(0xffffffffu, s, o);
        if (lane >= o) s += t;
    }
    if (lane == 31) wsum[wid] = s;
    __syncthreads();
    if (wid == 0) {
        int w = (lane < 8) ? wsum[lane] : 0;
        #pragma unroll
        for (int o = 1; o < 8; o <<= 1) {
            int t = __shfl_up_sync(0xffffffffu, w, o);
            if (lane >= o) w += t;
        }
        if (lane < 8) wsum[lane] = w;
    }
    __syncthreads();
    int excl = s - v + (wid > 0 ? wsum[wid - 1] : 0);
    if (threadIdx.x < NB) g_bsum[threadIdx.x] = excl;
    if (threadIdx.x == NB - 1) g_offs[N_NODES] = excl + v;
}

__global__ __launch_bounds__(SCAN_B) void k_scanC() {
    int i = blockIdx.x * SCAN_B + threadIdx.x;
    if (i < N_NODES) g_offs[i] += g_bsum[blockIdx.x];
}

__global__ void k_fill(const int* __restrict__ pos_ei) {
    int e = blockIdx.x * blockDim.x + threadIdx.x;
    if (e < N_POS) {
        int s = pos_ei[e];
        int d = pos_ei[N_POS + e];
        int p = g_offs[d] + atomicAdd(&g_cur[d], 1);
        g_esrc[p] = s;
    }
}

// =================================================================
// WMMA GEMM body: 64-column tile of C[nrows][OUTC] = A[nrows][128] @ W
// 128 threads = 4 warps x 32 rows = 128 rows/CTA. Each warp computes
// TWO 16-row tiles, so each B fragment pair feeds 6 MMAs (halves B
// ldmatrix traffic vs 1 row tile/warp). bf16 hi/lo 3-pass split.
// SA=40 / SWS=72: conflict-free ldmatrix, 16B-aligned rows.
// =================================================================
#define SA 40            // A smem stride (elems) — conflict-free
#define CTILE 64         // columns per CTA
#define SWS 72           // W smem stride (elems) — conflict-free

template <int OUTC>
__device__ __forceinline__ void wmma_body(const __nv_bfloat16* __restrict__ Ah,
                                          const __nv_bfloat16* __restrict__ Al,
                                          const __nv_bfloat16* __restrict__ Wh,
                                          const __nv_bfloat16* __restrict__ Wl,
                                          float* __restrict__ C, int nrows) {
    __shared__ alignas(256) __nv_bfloat16 sAh[128 * SA];
    __shared__ alignas(256) __nv_bfloat16 sAl[128 * SA];
    __shared__ alignas(256) __nv_bfloat16 sWh[32 * SWS];
    __shared__ alignas(256) __nv_bfloat16 sWl[32 * SWS];

    const int tid  = threadIdx.x;
    const int warp = tid >> 5;           // 0..3
    const int row0 = blockIdx.x * 128;
    const int col0 = blockIdx.y * CTILE;

    constexpr int NT = CTILE / 16;   // 4
    wmma::fragment<wmma::accumulator, 16, 16, 16, float> acc[2][NT];
    #pragma unroll
    for (int rt = 0; rt < 2; rt++)
        #pragma unroll
        for (int nt = 0; nt < NT; nt++) wmma::fill_fragment(acc[rt][nt], 0.0f);

    const uint4 uz = make_uint4(0u, 0u, 0u, 0u);

    for (int kb = 0; kb < 128; kb += 32) {
        // ---- stage A chunk [128 x 32]: pure vector copy of bf16 planes ----
        for (int idx = tid * 8; idx < 128 * 32; idx += 1024) {
            int r = idx >> 5, c = idx & 31;
            int grow = row0 + r;
            size_t goff = (size_t)grow * 128 + kb + c;
            uint4 vh = uz, vl = uz;
            if (grow < nrows) {
                vh = *(const uint4*)(Ah + goff);
                vl = *(const uint4*)(Al + goff);
            }
            *(uint4*)(sAh + r * SA + c) = vh;
            *(uint4*)(sAl + r * SA + c) = vl;
        }
        // ---- stage W chunk [32 x CTILE]: pure vector copy of bf16 planes ----
        for (int idx = tid * 8; idx < 32 * CTILE; idx += 1024) {
            int kr = idx / CTILE, n = idx % CTILE;
            *(uint4*)(sWh + kr * SWS + n) =
                *(const uint4*)(Wh + (size_t)(kb + kr) * OUTC + col0 + n);
            *(uint4*)(sWl + kr * SWS + n) =
                *(const uint4*)(Wl + (size_t)(kb + kr) * OUTC + col0 + n);
        }
        __syncthreads();

        #pragma unroll
        for (int kk = 0; kk < 32; kk += 16) {
            wmma::fragment<wmma::matrix_a, 16, 16, 16, __nv_bfloat16, wmma::row_major> fah[2], fal[2];
            #pragma unroll
            for (int rt = 0; rt < 2; rt++) {
                int r = warp * 32 + rt * 16;
                wmma::load_matrix_sync(fah[rt], sAh + r * SA + kk, SA);
                wmma::load_matrix_sync(fal[rt], sAl + r * SA + kk, SA);
            }
            #pragma unroll
            for (int nt = 0; nt < NT; nt++) {
                wmma::fragment<wmma::matrix_b, 16, 16, 16, __nv_bfloat16, wmma::row_major> fbh, fbl;
                wmma::load_matrix_sync(fbh, sWh + kk * SWS + nt * 16, SWS);
                wmma::load_matrix_sync(fbl, sWl + kk * SWS + nt * 16, SWS);
                #pragma unroll
                for (int rt = 0; rt < 2; rt++) {
                    wmma::mma_sync(acc[rt][nt], fah[rt], fbh, acc[rt][nt]);
                    wmma::mma_sync(acc[rt][nt], fah[rt], fbl, acc[rt][nt]);
                    wmma::mma_sync(acc[rt][nt], fal[rt], fbh, acc[rt][nt]);
                }
            }
        }
        __syncthreads();
    }

    #pragma unroll
    for (int rt = 0; rt < 2; rt++) {
        int wr = row0 + warp * 32 + rt * 16;
        if (wr + 16 <= nrows) {
            #pragma unroll
            for (int nt = 0; nt < NT; nt++)
                wmma::store_matrix_sync(C + (size_t)wr * OUTC + col0 + nt * 16, acc[rt][nt],
                                        OUTC, wmma::mem_row_major);
        }
    }
}

// wrapper kernels: device-side references to the __device__ globals
__global__ __launch_bounds__(128) void k_wmma1() {
    wmma_body<128>(gXh, gXl, gW1h, gW1l, g_h1, N_NODES);
}
__global__ __launch_bounds__(128) void k_wmma2() {
    wmma_body<64>(gZ1h, gZ1l, gW2h, gW2l, g_h2, N_NODES);
}

// ---------------- layer-1 aggregation: warp per dst node, 128 feats ----------------
// epilogue writes z1 directly as bf16 hi/lo planes (consumed by k_wmma2)
__global__ void k_agg1(const float* __restrict__ b1) {
    int gw = (blockIdx.x * blockDim.x + threadIdx.x) >> 5;
    int lane = threadIdx.x & 31;
    if (gw >= N_NODES) return;
    int d = gw;
    float dv = g_dinv[d];
    float self = dv * dv;

    float4 h = ((const float4*)(g_h1 + (size_t)d * 128))[lane];
    float4 acc = make_float4(h.x * self, h.y * self, h.z * self, h.w * self);

    int e0 = g_offs[d], e1 = g_offs[d + 1];
    int j = e0;
    for (; j + 4 <= e1; j += 4) {
        int s0 = g_esrc[j], s1 = g_esrc[j + 1], s2 = g_esrc[j + 2], s3 = g_esrc[j + 3];
        float n0 = dv * g_dinv[s0];
        float n1 = dv * g_dinv[s1];
        float n2 = dv * g_dinv[s2];
        float n3 = dv * g_dinv[s3];
        float4 v0 = ((const float4*)(g_h1 + (size_t)s0 * 128))[lane];
        float4 v1 = ((const float4*)(g_h1 + (size_t)s1 * 128))[lane];
        float4 v2 = ((const float4*)(g_h1 + (size_t)s2 * 128))[lane];
        float4 v3 = ((const float4*)(g_h1 + (size_t)s3 * 128))[lane];
        acc.x += v0.x * n0 + v1.x * n1 + v2.x * n2 + v3.x * n3;
        acc.y += v0.y * n0 + v1.y * n1 + v2.y * n2 + v3.y * n3;
        acc.z += v0.z * n0 + v1.z * n1 + v2.z * n2 + v3.z * n3;
        acc.w += v0.w * n0 + v1.w * n1 + v2.w * n2 + v3.w * n3;
    }
    for (; j < e1; j++) {
        int s0 = g_esrc[j];
        float n0 = dv * g_dinv[s0];
        float4 v0 = ((const float4*)(g_h1 + (size_t)s0 * 128))[lane];
        acc.x += v0.x * n0; acc.y += v0.y * n0;
        acc.z += v0.z * n0; acc.w += v0.w * n0;
    }
    float4 bb = ((const float4*)b1)[lane];
    acc.x = fmaxf(acc.x + bb.x, 0.0f);
    acc.y = fmaxf(acc.y + bb.y, 0.0f);
    acc.z = fmaxf(acc.z + bb.z, 0.0f);
    acc.w = fmaxf(acc.w + bb.w, 0.0f);
    uint2 hh, ll; cvt4(acc, hh, ll);
    ((uint2*)(gZ1h + (size_t)d * 128))[lane] = hh;
    ((uint2*)(gZ1l + (size_t)d * 128))[lane] = ll;
}

// ---------------- layer-2 aggregation: warp per dst node, 64 feats ----------------
__global__ void k_agg2(const float* __restrict__ b2) {
    int gw = (blockIdx.x * blockDim.x + threadIdx.x) >> 5;
    int lane = threadIdx.x & 31;
    if (gw >= N_NODES) return;
    int d = gw;
    float dv = g_dinv[d];
    float self = dv * dv;

    float2 h = ((const float2*)(g_h2 + (size_t)d * 64))[lane];
    float2 acc = make_float2(h.x * self, h.y * self);

    int e0 = g_offs[d], e1 = g_offs[d + 1];
    int j = e0;
    for (; j + 4 <= e1; j += 4) {
        int s0 = g_esrc[j], s1 = g_esrc[j + 1], s2 = g_esrc[j + 2], s3 = g_esrc[j + 3];
        float n0 = dv * g_dinv[s0];
        float n1 = dv * g_dinv[s1];
        float n2 = dv * g_dinv[s2];
        float n3 = dv * g_dinv[s3];
        float2 v0 = ((const float2*)(g_h2 + (size_t)s0 * 64))[lane];
        float2 v1 = ((const float2*)(g_h2 + (size_t)s1 * 64))[lane];
        float2 v2 = ((const float2*)(g_h2 + (size_t)s2 * 64))[lane];
        float2 v3 = ((const float2*)(g_h2 + (size_t)s3 * 64))[lane];
        acc.x += v0.x * n0 + v1.x * n1 + v2.x * n2 + v3.x * n3;
        acc.y += v0.y * n0 + v1.y * n1 + v2.y * n2 + v3.y * n3;
    }
    for (; j < e1; j++) {
        int s0 = g_esrc[j];
        float n0 = dv * g_dinv[s0];
        float2 v0 = ((const float2*)(g_h2 + (size_t)s0 * 64))[lane];
        acc.x += v0.x * n0; acc.y += v0.y * n0;
    }
    float2 bb = ((const float2*)b2)[lane];
    acc.x += bb.x; acc.y += bb.y;
    ((float2*)(g_z2 + (size_t)d * 64))[lane] = acc;
}

// ---------------- decode: warp per 2 edges, dot over 64 feats ----------------
__global__ void k_decode(const int* __restrict__ pos_ei,
                         const int* __restrict__ neg_ei,
                         float* __restrict__ out) {
    int w = (blockIdx.x * blockDim.x + threadIdx.x) >> 5;
    int lane = threadIdx.x & 31;
    int ea = w * 2;
    if (ea >= N_EDGES_TOT) return;
    int eb = ea + 1;
    bool has_b = (eb < N_EDGES_TOT);

    int a0, b0, a1 = 0, b1 = 0;
    if (ea < N_POS) { a0 = pos_ei[ea]; b0 = pos_ei[N_POS + ea]; }
    else { int f = ea - N_POS; a0 = neg_ei[f]; b0 = neg_ei[N_POS + f]; }
    if (has_b) {
        if (eb < N_POS) { a1 = pos_ei[eb]; b1 = pos_ei[N_POS + eb]; }
        else { int f = eb - N_POS; a1 = neg_ei[f]; b1 = neg_ei[N_POS + f]; }
    }

    float2 u0 = ((const float2*)(g_z2 + (size_t)a0 * 64))[lane];
    float2 v0 = ((const float2*)(g_z2 + (size_t)b0 * 64))[lane];
    float2 u1 = make_float2(0.f, 0.f), v1 = make_float2(0.f, 0.f);
    if (has_b) {
        u1 = ((const float2*)(g_z2 + (size_t)a1 * 64))[lane];
        v1 = ((const float2*)(g_z2 + (size_t)b1 * 64))[lane];
    }
    float s0 = u0.x * v0.x + u0.y * v0.y;
    float s1 = u1.x * v1.x + u1.y * v1.y;
    #pragma unroll
    for (int o = 16; o > 0; o >>= 1) {
        s0 += __shfl_xor_sync(0xffffffffu, s0, o);
        s1 += __shfl_xor_sync(0xffffffffu, s1, o);
    }
    if (lane == 0) {
        out[ea] = s0;
        if (has_b) out[eb] = s1;
    }
}

// ---------------- launch ----------------
extern "C" void kernel_launch(void* const* d_in, const int* in_sizes, int n_in,
                              void* d_out, int out_size) {
    const float* x   = (const float*)d_in[0];
    const int*   pos = (const int*)d_in[1];
    const int*   neg = (const int*)d_in[2];
    const float* W1  = (const float*)d_in[3];
    const float* b1  = (const float*)d_in[4];
    const float* W2  = (const float*)d_in[5];
    const float* b2  = (const float*)d_in[6];
    float* out = (float*)d_out;

    const int T = 256;
    const int GB = (N_NODES + 127) / 128;   // 782 row blocks

    // order chosen so launch #4 (ncu capture slot) is k_wmma1
    k_cvt<<<((N_NODES * 128) / 4 + T - 1) / T, T>>>(x, W1, W2);       // 1 (also zeroes cnt/cur)
    k_hist<<<(N_POS + T - 1) / T, T>>>(pos);                          // 2
    k_scanA<<<NB, SCAN_B>>>();                                        // 3
    k_wmma1<<<dim3(GB, 2), 128>>>();                                  // 4  <- profiled
    k_scanB<<<1, 256>>>();                                            // 5
    k_scanC<<<NB, SCAN_B>>>();                                        // 6
    k_fill<<<(N_POS + T - 1) / T, T>>>(pos);                          // 7
    k_agg1<<<(N_NODES * 32 + T - 1) / T, T>>>(b1);                    // 8
    k_wmma2<<<dim3(GB, 1), 128>>>();                                  // 9
    k_agg2<<<(N_NODES * 32 + T - 1) / T, T>>>(b2);                    // 10
    k_decode<<<((size_t)(N_EDGES_TOT / 2 + 1) * 32 + T - 1) / T, T>>>(pos, neg, out); // 11
}

// round 13
// speedup vs baseline: 1.0515x; 1.0515x over previous
#include <cuda_runtime.h>
#include <cuda_bf16.h>
#include <mma.h>
#include <math.h>
#include <stdint.h>

using namespace nvcuda;

#define N_NODES 100000
#define IN_CH   128
#define HIDDEN  128
#define OUT_CH  64
#define N_POS   600000
#define N_EDGES_TOT 1200000

#define SCAN_B 512
#define NB ((N_NODES + SCAN_B - 1) / SCAN_B)   // 196

// ---------------- scratch (no cudaMalloc allowed) ----------------
__device__ float g_h2[(size_t)N_NODES * OUT_CH];   // z1 @ W2
__device__ float g_z2[(size_t)N_NODES * OUT_CH];   // agg2 + b2
__device__ float g_dinv[N_NODES];
__device__ int   g_cnt[N_NODES];
__device__ int   g_cur[N_NODES];
__device__ int   g_offs[N_NODES + 1];
__device__ int   g_esrc[N_POS];
__device__ int   g_bsum[NB];
// bf16 hi/lo planes
__device__ __nv_bfloat16 gAXh[(size_t)N_NODES * 128], gAXl[(size_t)N_NODES * 128]; // agg(x)
__device__ __nv_bfloat16 gZ1h[(size_t)N_NODES * 128], gZ1l[(size_t)N_NODES * 128]; // relu(aggX@W1+b1)
__device__ __nv_bfloat16 gW1h[128 * 128], gW1l[128 * 128];
__device__ __nv_bfloat16 gW2h[128 * 64],  gW2l[128 * 64];

// ---------------- helpers ----------------
__device__ __forceinline__ uint32_t pack2(float a, float b) {
    uint32_t r;
    asm("cvt.rn.satfinite.bf16x2.f32 %0, %1, %2;" : "=r"(r) : "f"(b), "f"(a));
    return r;
}
__device__ __forceinline__ float bf16_round(float v) {
    return __bfloat162float(__float2bfloat16(v));
}
__device__ __forceinline__ void cvt4(float4 v, uint2& h, uint2& l) {
    h = make_uint2(pack2(v.x, v.y), pack2(v.z, v.w));
    l = make_uint2(pack2(v.x - bf16_round(v.x), v.y - bf16_round(v.y)),
                   pack2(v.z - bf16_round(v.z), v.w - bf16_round(v.w)));
}

// ---------------- prep: zero counters, convert W1/W2 to bf16 hi/lo planes ----------------
__global__ void k_prep(const float* __restrict__ W1, const float* __restrict__ W2) {
    int i = blockIdx.x * blockDim.x + threadIdx.x;
    if (i < N_NODES) { g_cnt[i] = 0; g_cur[i] = 0; }
    if (i < (128 * 128) / 4) {
        float4 v = ((const float4*)W1)[i];
        uint2 h, l; cvt4(v, h, l);
        ((uint2*)gW1h)[i] = h;
        ((uint2*)gW1l)[i] = l;
    }
    if (i < (128 * 64) / 4) {
        float4 v = ((const float4*)W2)[i];
        uint2 h, l; cvt4(v, h, l);
        ((uint2*)gW2h)[i] = h;
        ((uint2*)gW2l)[i] = l;
    }
}

__global__ void k_hist(const int* __restrict__ pos_ei) {
    int e = blockIdx.x * blockDim.x + threadIdx.x;
    if (e < N_POS) {
        int d = pos_ei[N_POS + e];
        atomicAdd(&g_cnt[d], 1);
    }
}

__global__ __launch_bounds__(SCAN_B) void k_scanA() {
    __shared__ int wsum[16];
    int i = blockIdx.x * SCAN_B + threadIdx.x;
    int lane = threadIdx.x & 31, wid = threadIdx.x >> 5;
    int v = (i < N_NODES) ? g_cnt[i] : 0;
    if (i < N_NODES) g_dinv[i] = rsqrtf((float)v + 1.0f);

    int s = v;
    #pragma unroll
    for (int o = 1; o < 32; o <<= 1) {
        int t = __shfl_up_sync(0xffffffffu, s, o);
        if (lane >= o) s += t;
    }
    if (lane == 31) wsum[wid] = s;
    __syncthreads();
    if (wid == 0) {
        int w = (lane < 16) ? wsum[lane] : 0;
        #pragma unroll
        for (int o = 1; o < 16; o <<= 1) {
            int t = __shfl_up_sync(0xffffffffu, w, o);
            if (lane >= o) w += t;
        }
        if (lane < 16) wsum[lane] = w;
    }
    __syncthreads();
    int excl = s - v + (wid > 0 ? wsum[wid - 1] : 0);
    if (i < N_NODES) g_offs[i] = excl;
    if (threadIdx.x == 0) g_bsum[blockIdx.x] = wsum[15];
}

__global__ __launch_bounds__(256) void k_scanB() {
    __shared__ int wsum[8];
    int lane = threadIdx.x & 31, wid = threadIdx.x >> 5;
    int v = (threadIdx.x < NB) ? g_bsum[threadIdx.x] : 0;
    int s = v;
    #pragma unroll
    for (int o = 1; o < 32; o <<= 1) {
        int t = __shfl_up_sync(0xffffffffu, s, o);
        if (lane >= o) s += t;
    }
    if (lane == 31) wsum[wid] = s;
    __syncthreads();
    if (wid == 0) {
        int w = (lane < 8) ? wsum[lane] : 0;
        #pragma unroll
        for (int o = 1; o < 8; o <<= 1) {
            int t = __shfl_up_sync(0xffffffffu, w, o);
            if (lane >= o) w += t;
        }
        if (lane < 8) wsum[lane] = w;
    }
    __syncthreads();
    int excl = s - v + (wid > 0 ? wsum[wid - 1] : 0);
    if (threadIdx.x < NB) g_bsum[threadIdx.x] = excl;
    if (threadIdx.x == NB - 1) g_offs[N_NODES] = excl + v;
}

__global__ __launch_bounds__(SCAN_B) void k_scanC() {
    int i = blockIdx.x * SCAN_B + threadIdx.x;
    if (i < N_NODES) g_offs[i] += g_bsum[blockIdx.x];
}

__global__ void k_fill(const int* __restrict__ pos_ei) {
    int e = blockIdx.x * blockDim.x + threadIdx.x;
    if (e < N_POS) {
        int s = pos_ei[e];
        int d = pos_ei[N_POS + e];
        int p = g_offs[d] + atomicAdd(&g_cur[d], 1);
        g_esrc[p] = s;
    }
}

// ---------------- layer-1 aggregation on RAW x (linearity: agg(x@W)=agg(x)@W) ----
// warp per dst node, 128 feats; writes agg(x) directly as bf16 hi/lo planes.
__global__ void k_aggX(const float* __restrict__ x) {
    int gw = (blockIdx.x * blockDim.x + threadIdx.x) >> 5;
    int lane = threadIdx.x & 31;
    if (gw >= N_NODES) return;
    int d = gw;
    float dv = g_dinv[d];
    float self = dv * dv;

    float4 h = ((const float4*)(x + (size_t)d * 128))[lane];
    float4 acc = make_float4(h.x * self, h.y * self, h.z * self, h.w * self);

    int e0 = g_offs[d], e1 = g_offs[d + 1];
    int j = e0;
    for (; j + 4 <= e1; j += 4) {
        int s0 = g_esrc[j], s1 = g_esrc[j + 1], s2 = g_esrc[j + 2], s3 = g_esrc[j + 3];
        float n0 = dv * g_dinv[s0];
        float n1 = dv * g_dinv[s1];
        float n2 = dv * g_dinv[s2];
        float n3 = dv * g_dinv[s3];
        float4 v0 = ((const float4*)(x + (size_t)s0 * 128))[lane];
        float4 v1 = ((const float4*)(x + (size_t)s1 * 128))[lane];
        float4 v2 = ((const float4*)(x + (size_t)s2 * 128))[lane];
        float4 v3 = ((const float4*)(x + (size_t)s3 * 128))[lane];
        acc.x += v0.x * n0 + v1.x * n1 + v2.x * n2 + v3.x * n3;
        acc.y += v0.y * n0 + v1.y * n1 + v2.y * n2 + v3.y * n3;
        acc.z += v0.z * n0 + v1.z * n1 + v2.z * n2 + v3.z * n3;
        acc.w += v0.w * n0 + v1.w * n1 + v2.w * n2 + v3.w * n3;
    }
    for (; j < e1; j++) {
        int s0 = g_esrc[j];
        float n0 = dv * g_dinv[s0];
        float4 v0 = ((const float4*)(x + (size_t)s0 * 128))[lane];
        acc.x += v0.x * n0; acc.y += v0.y * n0;
        acc.z += v0.z * n0; acc.w += v0.w * n0;
    }
    uint2 hh, ll; cvt4(acc, hh, ll);
    ((uint2*)(gAXh + (size_t)d * 128))[lane] = hh;
    ((uint2*)(gAXl + (size_t)d * 128))[lane] = ll;
}

// =================================================================
// WMMA GEMM body (R11 config: 8 warps x 16 rows, NT=4, SA=40/SWS=72).
// RELU=true:  out = relu(acc + bias) -> bf16 hi/lo planes Oh/Ol (stride 128)
// RELU=false: out = acc -> fp32 C (stride OUTC)
// =================================================================
#define SA 40            // A smem stride (elems) — conflict-free
#define CTILE 64         // columns per CTA
#define SWS 72           // W smem stride (elems) — conflict-free
#define SE 68            // epilogue fp32 scratch stride

template <int OUTC, bool RELU>
__device__ __forceinline__ void wmma_body(const __nv_bfloat16* __restrict__ Ah,
                                          const __nv_bfloat16* __restrict__ Al,
                                          const __nv_bfloat16* __restrict__ Wh,
                                          const __nv_bfloat16* __restrict__ Wl,
                                          float* __restrict__ C,
                                          __nv_bfloat16* __restrict__ Oh,
                                          __nv_bfloat16* __restrict__ Ol,
                                          const float* __restrict__ bias,
                                          int nrows) {
    constexpr int STAGE_BYTES = 128 * SA * 2 * 2 + 32 * SWS * 2 * 2;   // 29696
    constexpr int EPI_BYTES   = 128 * SE * 4;                          // 34816
    constexpr int SBYTES = RELU ? (STAGE_BYTES > EPI_BYTES ? STAGE_BYTES : EPI_BYTES)
                                : STAGE_BYTES;
    __shared__ alignas(256) unsigned char sraw[SBYTES];
    __nv_bfloat16* sAh = (__nv_bfloat16*)sraw;
    __nv_bfloat16* sAl = sAh + 128 * SA;
    __nv_bfloat16* sWh = sAl + 128 * SA;
    __nv_bfloat16* sWl = sWh + 32 * SWS;

    const int tid  = threadIdx.x;
    const int warp = tid >> 5;
    const int row0 = blockIdx.x * 128;
    const int col0 = blockIdx.y * CTILE;

    constexpr int NT = CTILE / 16;   // 4
    wmma::fragment<wmma::accumulator, 16, 16, 16, float> acc[NT];
    #pragma unroll
    for (int nt = 0; nt < NT; nt++) wmma::fill_fragment(acc[nt], 0.0f);

    const uint4 uz = make_uint4(0u, 0u, 0u, 0u);

    for (int kb = 0; kb < 128; kb += 32) {
        for (int idx = tid * 8; idx < 128 * 32; idx += 2048) {
            int r = idx >> 5, c = idx & 31;
            int grow = row0 + r;
            size_t goff = (size_t)grow * 128 + kb + c;
            uint4 vh = uz, vl = uz;
            if (grow < nrows) {
                vh = *(const uint4*)(Ah + goff);
                vl = *(const uint4*)(Al + goff);
            }
            *(uint4*)(sAh + r * SA + c) = vh;
            *(uint4*)(sAl + r * SA + c) = vl;
        }
        for (int idx = tid * 8; idx < 32 * CTILE; idx += 2048) {
            int kr = idx / CTILE, n = idx % CTILE;
            *(uint4*)(sWh + kr * SWS + n) =
                *(const uint4*)(Wh + (size_t)(kb + kr) * OUTC + col0 + n);
            *(uint4*)(sWl + kr * SWS + n) =
                *(const uint4*)(Wl + (size_t)(kb + kr) * OUTC + col0 + n);
        }
        __syncthreads();

        #pragma unroll
        for (int kk = 0; kk < 32; kk += 16) {
            wmma::fragment<wmma::matrix_a, 16, 16, 16, __nv_bfloat16, wmma::row_major> fah, fal;
            wmma::load_matrix_sync(fah, sAh + warp * 16 * SA + kk, SA);
            wmma::load_matrix_sync(fal, sAl + warp * 16 * SA + kk, SA);
            #pragma unroll
            for (int nt = 0; nt < NT; nt++) {
                wmma::fragment<wmma::matrix_b, 16, 16, 16, __nv_bfloat16, wmma::row_major> fbh, fbl;
                wmma::load_matrix_sync(fbh, sWh + kk * SWS + nt * 16, SWS);
                wmma::load_matrix_sync(fbl, sWl + kk * SWS + nt * 16, SWS);
                wmma::mma_sync(acc[nt], fah, fbh, acc[nt]);
                wmma::mma_sync(acc[nt], fah, fbl, acc[nt]);
                wmma::mma_sync(acc[nt], fal, fbh, acc[nt]);
            }
        }
        __syncthreads();
    }

    if (RELU) {
        // stage acc to fp32 smem, then bias+relu+cvt -> bf16 planes
        float* sC = (float*)sraw;
        #pragma unroll
        for (int nt = 0; nt < NT; nt++)
            wmma::store_matrix_sync(sC + warp * 16 * SE + nt * 16, acc[nt],
                                    SE, wmma::mem_row_major);
        __syncthreads();
        for (int idx = tid * 4; idx < 128 * CTILE; idx += 1024) {
            int r = idx >> 6, c = idx & 63;
            int grow = row0 + r;
            if (grow < nrows) {
                float4 v = *(float4*)(sC + r * SE + c);
                float4 bv = *(const float4*)(bias + col0 + c);
                v.x = fmaxf(v.x + bv.x, 0.0f);
                v.y = fmaxf(v.y + bv.y, 0.0f);
                v.z = fmaxf(v.z + bv.z, 0.0f);
                v.w = fmaxf(v.w + bv.w, 0.0f);
                uint2 h, l; cvt4(v, h, l);
                *(uint2*)(Oh + (size_t)grow * 128 + col0 + c) = h;
                *(uint2*)(Ol + (size_t)grow * 128 + col0 + c) = l;
            }
        }
    } else {
        int wr = row0 + warp * 16;
        if (wr + 16 <= nrows) {
            #pragma unroll
            for (int nt = 0; nt < NT; nt++)
                wmma::store_matrix_sync(C + (size_t)wr * OUTC + col0 + nt * 16, acc[nt],
                                        OUTC, wmma::mem_row_major);
        }
    }
}

// wrapper kernels: device-side references to the __device__ globals
__global__ __launch_bounds__(256) void k_wmma1(const float* __restrict__ b1) {
    wmma_body<128, true>(gAXh, gAXl, gW1h, gW1l, nullptr, gZ1h, gZ1l, b1, N_NODES);
}
__global__ __launch_bounds__(256) void k_wmma2() {
    wmma_body<64, false>(gZ1h, gZ1l, gW2h, gW2l, g_h2, nullptr, nullptr, nullptr, N_NODES);
}

// ---------------- layer-2 aggregation: warp per dst node, 64 feats ----------------
__global__ void k_agg2(const float* __restrict__ b2) {
    int gw = (blockIdx.x * blockDim.x + threadIdx.x) >> 5;
    int lane = threadIdx.x & 31;
    if (gw >= N_NODES) return;
    int d = gw;
    float dv = g_dinv[d];
    float self = dv * dv;

    float2 h = ((const float2*)(g_h2 + (size_t)d * 64))[lane];
    float2 acc = make_float2(h.x * self, h.y * self);

    int e0 = g_offs[d], e1 = g_offs[d + 1];
    int j = e0;
    for (; j + 4 <= e1; j += 4) {
        int s0 = g_esrc[j], s1 = g_esrc[j + 1], s2 = g_esrc[j + 2], s3 = g_esrc[j + 3];
        float n0 = dv * g_dinv[s0];
        float n1 = dv * g_dinv[s1];
        float n2 = dv * g_dinv[s2];
        float n3 = dv * g_dinv[s3];
        float2 v0 = ((const float2*)(g_h2 + (size_t)s0 * 64))[lane];
        float2 v1 = ((const float2*)(g_h2 + (size_t)s1 * 64))[lane];
        float2 v2 = ((const float2*)(g_h2 + (size_t)s2 * 64))[lane];
        float2 v3 = ((const float2*)(g_h2 + (size_t)s3 * 64))[lane];
        acc.x += v0.x * n0 + v1.x * n1 + v2.x * n2 + v3.x * n3;
        acc.y += v0.y * n0 + v1.y * n1 + v2.y * n2 + v3.y * n3;
    }
    for (; j < e1; j++) {
        int s0 = g_esrc[j];
        float n0 = dv * g_dinv[s0];
        float2 v0 = ((const float2*)(g_h2 + (size_t)s0 * 64))[lane];
        acc.x += v0.x * n0; acc.y += v0.y * n0;
    }
    float2 bb = ((const float2*)b2)[lane];
    acc.x += bb.x; acc.y += bb.y;
    ((float2*)(g_z2 + (size_t)d * 64))[lane] = acc;
}

// ---------------- decode: warp per 2 edges, dot over 64 feats ----------------
__global__ void k_decode(const int* __restrict__ pos_ei,
                         const int* __restrict__ neg_ei,
                         float* __restrict__ out) {
    int w = (blockIdx.x * blockDim.x + threadIdx.x) >> 5;
    int lane = threadIdx.x & 31;
    int ea = w * 2;
    if (ea >= N_EDGES_TOT) return;
    int eb = ea + 1;
    bool has_b = (eb < N_EDGES_TOT);

    int a0, b0, a1 = 0, b1 = 0;
    if (ea < N_POS) { a0 = pos_ei[ea]; b0 = pos_ei[N_POS + ea]; }
    else { int f = ea - N_POS; a0 = neg_ei[f]; b0 = neg_ei[N_POS + f]; }
    if (has_b) {
        if (eb < N_POS) { a1 = pos_ei[eb]; b1 = pos_ei[N_POS + eb]; }
        else { int f = eb - N_POS; a1 = neg_ei[f]; b1 = neg_ei[N_POS + f]; }
    }

    float2 u0 = ((const float2*)(g_z2 + (size_t)a0 * 64))[lane];
    float2 v0 = ((const float2*)(g_z2 + (size_t)b0 * 64))[lane];
    float2 u1 = make_float2(0.f, 0.f), v1 = make_float2(0.f, 0.f);
    if (has_b) {
        u1 = ((const float2*)(g_z2 + (size_t)a1 * 64))[lane];
        v1 = ((const float2*)(g_z2 + (size_t)b1 * 64))[lane];
    }
    float s0 = u0.x * v0.x + u0.y * v0.y;
    float s1 = u1.x * v1.x + u1.y * v1.y;
    #pragma unroll
    for (int o = 16; o > 0; o >>= 1) {
        s0 += __shfl_xor_sync(0xffffffffu, s0, o);
        s1 += __shfl_xor_sync(0xffffffffu, s1, o);
    }
    if (lane == 0) {
        out[ea] = s0;
        if (has_b) out[eb] = s1;
    }
}

// ---------------- launch ----------------
extern "C" void kernel_launch(void* const* d_in, const int* in_sizes, int n_in,
                              void* d_out, int out_size) {
    const float* x   = (const float*)d_in[0];
    const int*   pos = (const int*)d_in[1];
    const int*   neg = (const int*)d_in[2];
    const float* W1  = (const float*)d_in[3];
    const float* b1  = (const float*)d_in[4];
    const float* W2  = (const float*)d_in[5];
    const float* b2  = (const float*)d_in[6];
    float* out = (float*)d_out;

    const int T = 256;
    const int GB = (N_NODES + 127) / 128;   // 782 row blocks

    k_prep<<<(N_NODES + T - 1) / T, T>>>(W1, W2);                     // 1
    k_hist<<<(N_POS + T - 1) / T, T>>>(pos);                          // 2
    k_scanA<<<NB, SCAN_B>>>();                                        // 3
    k_scanB<<<1, 256>>>();                                            // 4
    k_scanC<<<NB, SCAN_B>>>();                                        // 5
    k_fill<<<(N_POS + T - 1) / T, T>>>(pos);                          // 6
    k_aggX<<<(N_NODES * 32 + T - 1) / T, T>>>(x);                     // 7
    k_wmma1<<<dim3(GB, 2), 256>>>(b1);                                // 8
    k_wmma2<<<dim3(GB, 1), 256>>>();                                  // 9
    k_agg2<<<(N_NODES * 32 + T - 1) / T, T>>>(b2);                    // 10
    k_decode<<<((size_t)(N_EDGES_TOT / 2 + 1) * 32 + T - 1) / T, T>>>(pos, neg, out); // 11
}

// round 14
// speedup vs baseline: 1.0617x; 1.0097x over previous
#include <cuda_runtime.h>
#include <cuda_bf16.h>
#include <mma.h>
#include <math.h>
#include <stdint.h>

using namespace nvcuda;

#define N_NODES 100000
#define IN_CH   128
#define HIDDEN  128
#define OUT_CH  64
#define N_POS   600000
#define N_EDGES_TOT 1200000

#define SCAN_B 512
#define NB ((N_NODES + SCAN_B - 1) / SCAN_B)   // 196

// ---------------- scratch (no cudaMalloc allowed) ----------------
__device__ float g_h2[(size_t)N_NODES * OUT_CH];   // z1 @ W2
__device__ float g_z2[(size_t)N_NODES * OUT_CH];   // agg2 + b2
__device__ float g_dinv[N_NODES];
__device__ int   g_cnt[N_NODES];
__device__ int   g_cur[N_NODES];
__device__ int   g_offs[N_NODES + 1];   // block-LOCAL exclusive prefixes
__device__ int   g_esrc[N_POS];
__device__ int   g_bsum[NB];            // exclusive block prefix (after scanB)
// bf16 hi/lo planes
__device__ __nv_bfloat16 gAXh[(size_t)N_NODES * 128], gAXl[(size_t)N_NODES * 128]; // agg(x)
__device__ __nv_bfloat16 gZ1h[(size_t)N_NODES * 128], gZ1l[(size_t)N_NODES * 128]; // relu(aggX@W1+b1)
__device__ __nv_bfloat16 gW1h[128 * 128], gW1l[128 * 128];
__device__ __nv_bfloat16 gW2h[128 * 64],  gW2l[128 * 64];

// ---------------- helpers ----------------
__device__ __forceinline__ uint32_t pack2(float a, float b) {
    uint32_t r;
    asm("cvt.rn.satfinite.bf16x2.f32 %0, %1, %2;" : "=r"(r) : "f"(b), "f"(a));
    return r;
}
__device__ __forceinline__ float bf16_round(float v) {
    return __bfloat162float(__float2bfloat16(v));
}
__device__ __forceinline__ void cvt4(float4 v, uint2& h, uint2& l) {
    h = make_uint2(pack2(v.x, v.y), pack2(v.z, v.w));
    l = make_uint2(pack2(v.x - bf16_round(v.x), v.y - bf16_round(v.y)),
                   pack2(v.z - bf16_round(v.z), v.w - bf16_round(v.w)));
}

// ---------------- prep: zero counters, convert W1/W2 to bf16 hi/lo planes ----------------
__global__ void k_prep(const float* __restrict__ W1, const float* __restrict__ W2) {
    int i = blockIdx.x * blockDim.x + threadIdx.x;
    if (i < N_NODES) { g_cnt[i] = 0; g_cur[i] = 0; }
    if (i < (128 * 128) / 4) {
        float4 v = ((const float4*)W1)[i];
        uint2 h, l; cvt4(v, h, l);
        ((uint2*)gW1h)[i] = h;
        ((uint2*)gW1l)[i] = l;
    }
    if (i < (128 * 64) / 4) {
        float4 v = ((const float4*)W2)[i];
        uint2 h, l; cvt4(v, h, l);
        ((uint2*)gW2h)[i] = h;
        ((uint2*)gW2l)[i] = l;
    }
}

__global__ void k_hist(const int* __restrict__ pos_ei) {
    int e = blockIdx.x * blockDim.x + threadIdx.x;
    if (e < N_POS) {
        int d = pos_ei[N_POS + e];
        atomicAdd(&g_cnt[d], 1);
    }
}

// scanA: block-local exclusive scan. Writes offs for i <= N_NODES so the
// d+1 == N_NODES boundary lookup works with late-bound block offsets.
__global__ __launch_bounds__(SCAN_B) void k_scanA() {
    __shared__ int wsum[16];
    int i = blockIdx.x * SCAN_B + threadIdx.x;
    int lane = threadIdx.x & 31, wid = threadIdx.x >> 5;
    int v = (i < N_NODES) ? g_cnt[i] : 0;
    if (i < N_NODES) g_dinv[i] = rsqrtf((float)v + 1.0f);

    int s = v;
    #pragma unroll
    for (int o = 1; o < 32; o <<= 1) {
        int t = __shfl_up_sync(0xffffffffu, s, o);
        if (lane >= o) s += t;
    }
    if (lane == 31) wsum[wid] = s;
    __syncthreads();
    if (wid == 0) {
        int w = (lane < 16) ? wsum[lane] : 0;
        #pragma unroll
        for (int o = 1; o < 16; o <<= 1) {
            int t = __shfl_up_sync(0xffffffffu, w, o);
            if (lane >= o) w += t;
        }
        if (lane < 16) wsum[lane] = w;
    }
    __syncthreads();
    int excl = s - v + (wid > 0 ? wsum[wid - 1] : 0);
    if (i <= N_NODES) g_offs[i] = excl;           // block-LOCAL exclusive
    if (threadIdx.x == 0) g_bsum[blockIdx.x] = wsum[15];
}

// scanB: exclusive scan of block sums (in place). Consumers add bsum lazily.
__global__ __launch_bounds__(256) void k_scanB() {
    __shared__ int wsum[8];
    int lane = threadIdx.x & 31, wid = threadIdx.x >> 5;
    int v = (threadIdx.x < NB) ? g_bsum[threadIdx.x] : 0;
    int s = v;
    #pragma unroll
    for (int o = 1; o < 32; o <<= 1) {
        int t = __shfl_up_sync(0xffffffffu, s, o);
        if (lane >= o) s += t;
    }
    if (lane == 31) wsum[wid] = s;
    __syncthreads();
    if (wid == 0) {
        int w = (lane < 8) ? wsum[lane] : 0;
        #pragma unroll
        for (int o = 1; o < 8; o <<= 1) {
            int t = __shfl_up_sync(0xffffffffu, w, o);
            if (lane >= o) w += t;
        }
        if (lane < 8) wsum[lane] = w;
    }
    __syncthreads();
    int excl = s - v + (wid > 0 ? wsum[wid - 1] : 0);
    if (threadIdx.x < NB) g_bsum[threadIdx.x] = excl;
}

__device__ __forceinline__ int edge_off(int i) {   // final CSR offset for node/boundary i
    return g_offs[i] + g_bsum[i >> 9];
}

__global__ void k_fill(const int* __restrict__ pos_ei) {
    int e = blockIdx.x * blockDim.x + threadIdx.x;
    if (e < N_POS) {
        int s = pos_ei[e];
        int d = pos_ei[N_POS + e];
        int p = edge_off(d) + atomicAdd(&g_cur[d], 1);
        g_esrc[p] = s;
    }
}

// ---------------- layer-1 aggregation on RAW x (linearity: agg(x@W)=agg(x)@W) ----
// warp per dst node, 128 feats; writes agg(x) directly as bf16 hi/lo planes.
__global__ void k_aggX(const float* __restrict__ x) {
    int gw = (blockIdx.x * blockDim.x + threadIdx.x) >> 5;
    int lane = threadIdx.x & 31;
    if (gw >= N_NODES) return;
    int d = gw;
    float dv = g_dinv[d];
    float self = dv * dv;

    float4 h = ((const float4*)(x + (size_t)d * 128))[lane];
    float4 acc = make_float4(h.x * self, h.y * self, h.z * self, h.w * self);

    int e0 = edge_off(d), e1 = edge_off(d + 1);
    int j = e0;
    for (; j + 4 <= e1; j += 4) {
        int s0 = g_esrc[j], s1 = g_esrc[j + 1], s2 = g_esrc[j + 2], s3 = g_esrc[j + 3];
        float n0 = dv * g_dinv[s0];
        float n1 = dv * g_dinv[s1];
        float n2 = dv * g_dinv[s2];
        float n3 = dv * g_dinv[s3];
        float4 v0 = ((const float4*)(x + (size_t)s0 * 128))[lane];
        float4 v1 = ((const float4*)(x + (size_t)s1 * 128))[lane];
        float4 v2 = ((const float4*)(x + (size_t)s2 * 128))[lane];
        float4 v3 = ((const float4*)(x + (size_t)s3 * 128))[lane];
        acc.x += v0.x * n0 + v1.x * n1 + v2.x * n2 + v3.x * n3;
        acc.y += v0.y * n0 + v1.y * n1 + v2.y * n2 + v3.y * n3;
        acc.z += v0.z * n0 + v1.z * n1 + v2.z * n2 + v3.z * n3;
        acc.w += v0.w * n0 + v1.w * n1 + v2.w * n2 + v3.w * n3;
    }
    for (; j < e1; j++) {
        int s0 = g_esrc[j];
        float n0 = dv * g_dinv[s0];
        float4 v0 = ((const float4*)(x + (size_t)s0 * 128))[lane];
        acc.x += v0.x * n0; acc.y += v0.y * n0;
        acc.z += v0.z * n0; acc.w += v0.w * n0;
    }
    uint2 hh, ll; cvt4(acc, hh, ll);
    ((uint2*)(gAXh + (size_t)d * 128))[lane] = hh;
    ((uint2*)(gAXl + (size_t)d * 128))[lane] = ll;
}

// =================================================================
// WMMA GEMM body (8 warps x 16 rows, NT=4, SA=40/SWS=72, 4 CTAs/SM).
// RELU=true:  out = relu(acc + bias) -> bf16 hi/lo planes Oh/Ol (stride 128)
// RELU=false: out = acc -> fp32 C (stride OUTC)
// =================================================================
#define SA 40            // A smem stride (elems) — conflict-free
#define CTILE 64         // columns per CTA
#define SWS 72           // W smem stride (elems) — conflict-free
#define SE 68            // epilogue fp32 scratch stride

template <int OUTC, bool RELU>
__device__ __forceinline__ void wmma_body(const __nv_bfloat16* __restrict__ Ah,
                                          const __nv_bfloat16* __restrict__ Al,
                                          const __nv_bfloat16* __restrict__ Wh,
                                          const __nv_bfloat16* __restrict__ Wl,
                                          float* __restrict__ C,
                                          __nv_bfloat16* __restrict__ Oh,
                                          __nv_bfloat16* __restrict__ Ol,
                                          const float* __restrict__ bias,
                                          int nrows) {
    constexpr int STAGE_BYTES = 128 * SA * 2 * 2 + 32 * SWS * 2 * 2;   // 29696
    constexpr int EPI_BYTES   = 128 * SE * 4;                          // 34816
    constexpr int SBYTES = RELU ? (STAGE_BYTES > EPI_BYTES ? STAGE_BYTES : EPI_BYTES)
                                : STAGE_BYTES;
    __shared__ alignas(256) unsigned char sraw[SBYTES];
    __nv_bfloat16* sAh = (__nv_bfloat16*)sraw;
    __nv_bfloat16* sAl = sAh + 128 * SA;
    __nv_bfloat16* sWh = sAl + 128 * SA;
    __nv_bfloat16* sWl = sWh + 32 * SWS;

    const int tid  = threadIdx.x;
    const int warp = tid >> 5;
    const int row0 = blockIdx.x * 128;
    const int col0 = blockIdx.y * CTILE;

    constexpr int NT = CTILE / 16;   // 4
    wmma::fragment<wmma::accumulator, 16, 16, 16, float> acc[NT];
    #pragma unroll
    for (int nt = 0; nt < NT; nt++) wmma::fill_fragment(acc[nt], 0.0f);

    const uint4 uz = make_uint4(0u, 0u, 0u, 0u);

    for (int kb = 0; kb < 128; kb += 32) {
        for (int idx = tid * 8; idx < 128 * 32; idx += 2048) {
            int r = idx >> 5, c = idx & 31;
            int grow = row0 + r;
            size_t goff = (size_t)grow * 128 + kb + c;
            uint4 vh = uz, vl = uz;
            if (grow < nrows) {
                vh = *(const uint4*)(Ah + goff);
                vl = *(const uint4*)(Al + goff);
            }
            *(uint4*)(sAh + r * SA + c) = vh;
            *(uint4*)(sAl + r * SA + c) = vl;
        }
        for (int idx = tid * 8; idx < 32 * CTILE; idx += 2048) {
            int kr = idx / CTILE, n = idx % CTILE;
            *(uint4*)(sWh + kr * SWS + n) =
                *(const uint4*)(Wh + (size_t)(kb + kr) * OUTC + col0 + n);
            *(uint4*)(sWl + kr * SWS + n) =
                *(const uint4*)(Wl + (size_t)(kb + kr) * OUTC + col0 + n);
        }
        __syncthreads();

        #pragma unroll
        for (int kk = 0; kk < 32; kk += 16) {
            wmma::fragment<wmma::matrix_a, 16, 16, 16, __nv_bfloat16, wmma::row_major> fah, fal;
            wmma::load_matrix_sync(fah, sAh + warp * 16 * SA + kk, SA);
            wmma::load_matrix_sync(fal, sAl + warp * 16 * SA + kk, SA);
            #pragma unroll
            for (int nt = 0; nt < NT; nt++) {
                wmma::fragment<wmma::matrix_b, 16, 16, 16, __nv_bfloat16, wmma::row_major> fbh, fbl;
                wmma::load_matrix_sync(fbh, sWh + kk * SWS + nt * 16, SWS);
                wmma::load_matrix_sync(fbl, sWl + kk * SWS + nt * 16, SWS);
                wmma::mma_sync(acc[nt], fah, fbh, acc[nt]);
                wmma::mma_sync(acc[nt], fah, fbl, acc[nt]);
                wmma::mma_sync(acc[nt], fal, fbh, acc[nt]);
            }
        }
        __syncthreads();
    }

    if (RELU) {
        float* sC = (float*)sraw;
        #pragma unroll
        for (int nt = 0; nt < NT; nt++)
            wmma::store_matrix_sync(sC + warp * 16 * SE + nt * 16, acc[nt],
                                    SE, wmma::mem_row_major);
        __syncthreads();
        for (int idx = tid * 4; idx < 128 * CTILE; idx += 1024) {
            int r = idx >> 6, c = idx & 63;
            int grow = row0 + r;
            if (grow < nrows) {
                float4 v = *(float4*)(sC + r * SE + c);
                float4 bv = *(const float4*)(bias + col0 + c);
                v.x = fmaxf(v.x + bv.x, 0.0f);
                v.y = fmaxf(v.y + bv.y, 0.0f);
                v.z = fmaxf(v.z + bv.z, 0.0f);
                v.w = fmaxf(v.w + bv.w, 0.0f);
                uint2 h, l; cvt4(v, h, l);
                *(uint2*)(Oh + (size_t)grow * 128 + col0 + c) = h;
                *(uint2*)(Ol + (size_t)grow * 128 + col0 + c) = l;
            }
        }
    } else {
        int wr = row0 + warp * 16;
        if (wr + 16 <= nrows) {
            #pragma unroll
            for (int nt = 0; nt < NT; nt++)
                wmma::store_matrix_sync(C + (size_t)wr * OUTC + col0 + nt * 16, acc[nt],
                                        OUTC, wmma::mem_row_major);
        }
    }
}

// wrapper kernels: device-side references to the __device__ globals
__global__ __launch_bounds__(256, 4) void k_wmma1(const float* __restrict__ b1) {
    wmma_body<128, true>(gAXh, gAXl, gW1h, gW1l, nullptr, gZ1h, gZ1l, b1, N_NODES);
}
__global__ __launch_bounds__(256, 4) void k_wmma2() {
    wmma_body<64, false>(gZ1h, gZ1l, gW2h, gW2l, g_h2, nullptr, nullptr, nullptr, N_NODES);
}

// ---------------- layer-2 aggregation: warp per dst node, 64 feats ----------------
__global__ void k_agg2(const float* __restrict__ b2) {
    int gw = (blockIdx.x * blockDim.x + threadIdx.x) >> 5;
    int lane = threadIdx.x & 31;
    if (gw >= N_NODES) return;
    int d = gw;
    float dv = g_dinv[d];
    float self = dv * dv;

    float2 h = ((const float2*)(g_h2 + (size_t)d * 64))[lane];
    float2 acc = make_float2(h.x * self, h.y * self);

    int e0 = edge_off(d), e1 = edge_off(d + 1);
    int j = e0;
    for (; j + 4 <= e1; j += 4) {
        int s0 = g_esrc[j], s1 = g_esrc[j + 1], s2 = g_esrc[j + 2], s3 = g_esrc[j + 3];
        float n0 = dv * g_dinv[s0];
        float n1 = dv * g_dinv[s1];
        float n2 = dv * g_dinv[s2];
        float n3 = dv * g_dinv[s3];
        float2 v0 = ((const float2*)(g_h2 + (size_t)s0 * 64))[lane];
        float2 v1 = ((const float2*)(g_h2 + (size_t)s1 * 64))[lane];
        float2 v2 = ((const float2*)(g_h2 + (size_t)s2 * 64))[lane];
        float2 v3 = ((const float2*)(g_h2 + (size_t)s3 * 64))[lane];
        acc.x += v0.x * n0 + v1.x * n1 + v2.x * n2 + v3.x * n3;
        acc.y += v0.y * n0 + v1.y * n1 + v2.y * n2 + v3.y * n3;
    }
    for (; j < e1; j++) {
        int s0 = g_esrc[j];
        float n0 = dv * g_dinv[s0];
        float2 v0 = ((const float2*)(g_h2 + (size_t)s0 * 64))[lane];
        acc.x += v0.x * n0; acc.y += v0.y * n0;
    }
    float2 bb = ((const float2*)b2)[lane];
    acc.x += bb.x; acc.y += bb.y;
    ((float2*)(g_z2 + (size_t)d * 64))[lane] = acc;
}

// ---------------- decode: warp per 2 edges, dot over 64 feats ----------------
__global__ void k_decode(const int* __restrict__ pos_ei,
                         const int* __restrict__ neg_ei,
                         float* __restrict__ out) {
    int w = (blockIdx.x * blockDim.x + threadIdx.x) >> 5;
    int lane = threadIdx.x & 31;
    int ea = w * 2;
    if (ea >= N_EDGES_TOT) return;
    int eb = ea + 1;
    bool has_b = (eb < N_EDGES_TOT);

    int a0, b0, a1 = 0, b1 = 0;
    if (ea < N_POS) { a0 = pos_ei[ea]; b0 = pos_ei[N_POS + ea]; }
    else { int f = ea - N_POS; a0 = neg_ei[f]; b0 = neg_ei[N_POS + f]; }
    if (has_b) {
        if (eb < N_POS) { a1 = pos_ei[eb]; b1 = pos_ei[N_POS + eb]; }
        else { int f = eb - N_POS; a1 = neg_ei[f]; b1 = neg_ei[N_POS + f]; }
    }

    float2 u0 = ((const float2*)(g_z2 + (size_t)a0 * 64))[lane];
    float2 v0 = ((const float2*)(g_z2 + (size_t)b0 * 64))[lane];
    float2 u1 = make_float2(0.f, 0.f), v1 = make_float2(0.f, 0.f);
    if (has_b) {
        u1 = ((const float2*)(g_z2 + (size_t)a1 * 64))[lane];
        v1 = ((const float2*)(g_z2 + (size_t)b1 * 64))[lane];
    }
    float s0 = u0.x * v0.x + u0.y * v0.y;
    float s1 = u1.x * v1.x + u1.y * v1.y;
    #pragma unroll
    for (int o = 16; o > 0; o >>= 1) {
        s0 += __shfl_xor_sync(0xffffffffu, s0, o);
        s1 += __shfl_xor_sync(0xffffffffu, s1, o);
    }
    if (lane == 0) {
        out[ea] = s0;
        if (has_b) out[eb] = s1;
    }
}

// ---------------- launch ----------------
extern "C" void kernel_launch(void* const* d_in, const int* in_sizes, int n_in,
                              void* d_out, int out_size) {
    const float* x   = (const float*)d_in[0];
    const int*   pos = (const int*)d_in[1];
    const int*   neg = (const int*)d_in[2];
    const float* W1  = (const float*)d_in[3];
    const float* b1  = (const float*)d_in[4];
    const float* W2  = (const float*)d_in[5];
    const float* b2  = (const float*)d_in[6];
    float* out = (float*)d_out;

    const int T = 256;
    const int GB = (N_NODES + 127) / 128;   // 782 row blocks

    k_prep<<<(N_NODES + T - 1) / T, T>>>(W1, W2);                     // 1
    k_hist<<<(N_POS + T - 1) / T, T>>>(pos);                          // 2
    k_scanA<<<NB, SCAN_B>>>();                                        // 3
    k_scanB<<<1, 256>>>();                                            // 4
    k_fill<<<(N_POS + T - 1) / T, T>>>(pos);                          // 5
    k_aggX<<<(N_NODES * 32 + T - 1) / T, T>>>(x);                     // 6
    k_wmma1<<<dim3(GB, 2), 256>>>(b1);                                // 7
    k_wmma2<<<dim3(GB, 1), 256>>>();                                  // 8
    k_agg2<<<(N_NODES * 32 + T - 1) / T, T>>>(b2);                    // 9
    k_decode<<<((size_t)(N_EDGES_TOT / 2 + 1) * 32 + T - 1) / T, T>>>(pos, neg, out); // 10
}

// round 15
// speedup vs baseline: 1.1312x; 1.0654x over previous
#include <cuda_runtime.h>
#include <cuda_bf16.h>
#include <mma.h>
#include <math.h>
#include <stdint.h>

using namespace nvcuda;

#define N_NODES 100000
#define IN_CH   128
#define HIDDEN  128
#define OUT_CH  64
#define N_POS   600000
#define N_EDGES_TOT 1200000

#define SCAN_B 512
#define NB ((N_NODES + SCAN_B - 1) / SCAN_B)   // 196

// ---------------- scratch (no cudaMalloc allowed) ----------------
__device__ float g_h2[(size_t)N_NODES * OUT_CH];   // z1 @ W2
__device__ float g_z2[(size_t)N_NODES * OUT_CH];   // agg2 + b2
__device__ float g_dinv[N_NODES];
__device__ int   g_cnt[N_NODES];     // zeroed by decode (prev run) / module init
__device__ int   g_cur[N_NODES];
__device__ int   g_offs[N_NODES + 1];   // block-LOCAL exclusive prefixes
__device__ int   g_esrc[N_POS];
__device__ int   g_bsum[NB];            // exclusive block prefix (after scanB)
// bf16 hi/lo planes
__device__ __nv_bfloat16 gAXh[(size_t)N_NODES * 128], gAXl[(size_t)N_NODES * 128]; // agg(x)
__device__ __nv_bfloat16 gZ1h[(size_t)N_NODES * 128], gZ1l[(size_t)N_NODES * 128]; // relu(aggX@W1+b1)
__device__ __nv_bfloat16 gW1h[128 * 128], gW1l[128 * 128];
__device__ __nv_bfloat16 gW2h[128 * 64],  gW2l[128 * 64];

// ---------------- helpers ----------------
__device__ __forceinline__ uint32_t pack2(float a, float b) {
    uint32_t r;
    asm("cvt.rn.satfinite.bf16x2.f32 %0, %1, %2;" : "=r"(r) : "f"(b), "f"(a));
    return r;
}
__device__ __forceinline__ float bf16_round(float v) {
    return __bfloat162float(__float2bfloat16(v));
}
__device__ __forceinline__ void cvt4(float4 v, uint2& h, uint2& l) {
    h = make_uint2(pack2(v.x, v.y), pack2(v.z, v.w));
    l = make_uint2(pack2(v.x - bf16_round(v.x), v.y - bf16_round(v.y)),
                   pack2(v.z - bf16_round(v.z), v.w - bf16_round(v.w)));
}
__device__ __forceinline__ uint32_t smem_u32(const void* p) {
    uint32_t a;
    asm("{ .reg .u64 t; cvta.to.shared.u64 t, %1; cvt.u32.u64 %0, t; }" : "=r"(a) : "l"(p));
    return a;
}
__device__ __forceinline__ void cp16(uint32_t dst, const void* src, int nbytes) {
    asm volatile("cp.async.cg.shared.global [%0], [%1], 16, %2;"
                 :: "r"(dst), "l"(src), "r"(nbytes) : "memory");
}
#define CP_COMMIT() asm volatile("cp.async.commit_group;" ::: "memory")
#define CP_WAIT1()  asm volatile("cp.async.wait_group 1;" ::: "memory")
#define CP_WAIT0()  asm volatile("cp.async.wait_group 0;" ::: "memory")

// ---------------- prep: convert W1/W2 to bf16 hi/lo planes + histogram ----------------
__global__ void k_prep(const int* __restrict__ pos_ei,
                       const float* __restrict__ W1,
                       const float* __restrict__ W2) {
    int i = blockIdx.x * blockDim.x + threadIdx.x;
    if (i < (128 * 128) / 4) {
        float4 v = ((const float4*)W1)[i];
        uint2 h, l; cvt4(v, h, l);
        ((uint2*)gW1h)[i] = h;
        ((uint2*)gW1l)[i] = l;
    }
    if (i < (128 * 64) / 4) {
        float4 v = ((const float4*)W2)[i];
        uint2 h, l; cvt4(v, h, l);
        ((uint2*)gW2h)[i] = h;
        ((uint2*)gW2l)[i] = l;
    }
    if (i < N_POS) {
        int d = pos_ei[N_POS + i];
        atomicAdd(&g_cnt[d], 1);
    }
}

// scanA: block-local exclusive scan (writes i <= N_NODES for boundary lookup)
__global__ __launch_bounds__(SCAN_B) void k_scanA() {
    __shared__ int wsum[16];
    int i = blockIdx.x * SCAN_B + threadIdx.x;
    int lane = threadIdx.x & 31, wid = threadIdx.x >> 5;
    int v = (i < N_NODES) ? g_cnt[i] : 0;
    if (i < N_NODES) g_dinv[i] = rsqrtf((float)v + 1.0f);

    int s = v;
    #pragma unroll
    for (int o = 1; o < 32; o <<= 1) {
        int t = __shfl_up_sync(0xffffffffu, s, o);
        if (lane >= o) s += t;
    }
    if (lane == 31) wsum[wid] = s;
    __syncthreads();
    if (wid == 0) {
        int w = (lane < 16) ? wsum[lane] : 0;
        #pragma unroll
        for (int o = 1; o < 16; o <<= 1) {
            int t = __shfl_up_sync(0xffffffffu, w, o);
            if (lane >= o) w += t;
        }
        if (lane < 16) wsum[lane] = w;
    }
    __syncthreads();
    int excl = s - v + (wid > 0 ? wsum[wid - 1] : 0);
    if (i <= N_NODES) g_offs[i] = excl;
    if (threadIdx.x == 0) g_bsum[blockIdx.x] = wsum[15];
}

// scanB: exclusive scan of block sums (in place)
__global__ __launch_bounds__(256) void k_scanB() {
    __shared__ int wsum[8];
    int lane = threadIdx.x & 31, wid = threadIdx.x >> 5;
    int v = (threadIdx.x < NB) ? g_bsum[threadIdx.x] : 0;
    int s = v;
    #pragma unroll
    for (int o = 1; o < 32; o <<= 1) {
        int t = __shfl_up_sync(0xffffffffu, s, o);
        if (lane >= o) s += t;
    }
    if (lane == 31) wsum[wid] = s;
    __syncthreads();
    if (wid == 0) {
        int w = (lane < 8) ? wsum[lane] : 0;
        #pragma unroll
        for (int o = 1; o < 8; o <<= 1) {
            int t = __shfl_up_sync(0xffffffffu, w, o);
            if (lane >= o) w += t;
        }
        if (lane < 8) wsum[lane] = w;
    }
    __syncthreads();
    int excl = s - v + (wid > 0 ? wsum[wid - 1] : 0);
    if (threadIdx.x < NB) g_bsum[threadIdx.x] = excl;
}

__device__ __forceinline__ int edge_off(int i) {
    return g_offs[i] + g_bsum[i >> 9];
}

__global__ void k_fill(const int* __restrict__ pos_ei) {
    int e = blockIdx.x * blockDim.x + threadIdx.x;
    if (e < N_POS) {
        int s = pos_ei[e];
        int d = pos_ei[N_POS + e];
        int p = edge_off(d) + atomicAdd(&g_cur[d], 1);
        g_esrc[p] = s;
    }
}

// ---------------- layer-1 aggregation on RAW x (agg(x@W)=agg(x)@W) ----
__global__ void k_aggX(const float* __restrict__ x) {
    int gw = (blockIdx.x * blockDim.x + threadIdx.x) >> 5;
    int lane = threadIdx.x & 31;
    if (gw >= N_NODES) return;
    int d = gw;
    float dv = g_dinv[d];
    float self = dv * dv;

    float4 h = ((const float4*)(x + (size_t)d * 128))[lane];
    float4 acc = make_float4(h.x * self, h.y * self, h.z * self, h.w * self);

    int e0 = edge_off(d), e1 = edge_off(d + 1);
    int j = e0;
    for (; j + 4 <= e1; j += 4) {
        int s0 = g_esrc[j], s1 = g_esrc[j + 1], s2 = g_esrc[j + 2], s3 = g_esrc[j + 3];
        float n0 = dv * g_dinv[s0];
        float n1 = dv * g_dinv[s1];
        float n2 = dv * g_dinv[s2];
        float n3 = dv * g_dinv[s3];
        float4 v0 = ((const float4*)(x + (size_t)s0 * 128))[lane];
        float4 v1 = ((const float4*)(x + (size_t)s1 * 128))[lane];
        float4 v2 = ((const float4*)(x + (size_t)s2 * 128))[lane];
        float4 v3 = ((const float4*)(x + (size_t)s3 * 128))[lane];
        acc.x += v0.x * n0 + v1.x * n1 + v2.x * n2 + v3.x * n3;
        acc.y += v0.y * n0 + v1.y * n1 + v2.y * n2 + v3.y * n3;
        acc.z += v0.z * n0 + v1.z * n1 + v2.z * n2 + v3.z * n3;
        acc.w += v0.w * n0 + v1.w * n1 + v2.w * n2 + v3.w * n3;
    }
    for (; j < e1; j++) {
        int s0 = g_esrc[j];
        float n0 = dv * g_dinv[s0];
        float4 v0 = ((const float4*)(x + (size_t)s0 * 128))[lane];
        acc.x += v0.x * n0; acc.y += v0.y * n0;
        acc.z += v0.z * n0; acc.w += v0.w * n0;
    }
    uint2 hh, ll; cvt4(acc, hh, ll);
    ((uint2*)(gAXh + (size_t)d * 128))[lane] = hh;
    ((uint2*)(gAXl + (size_t)d * 128))[lane] = ll;
}

// =================================================================
// WMMA GEMM body: cp.async double-buffered, k-chunk=16, 8 warps x 16 rows.
// SA16=24 / SWS=72: conflict-free ldmatrix, 16B-aligned rows.
// RELU=true:  out = relu(acc + bias) -> bf16 hi/lo planes (stride 128)
// RELU=false: out = acc -> fp32 C (stride OUTC)
// =================================================================
#define SA16 24          // A smem stride (elems), chunk k=16
#define CTILE 64         // columns per CTA
#define SWS 72           // W smem stride (elems)
#define SE 68            // epilogue fp32 scratch stride

template <int OUTC, bool RELU>
__device__ __forceinline__ void wmma_body(const __nv_bfloat16* __restrict__ Ah,
                                          const __nv_bfloat16* __restrict__ Al,
                                          const __nv_bfloat16* __restrict__ Wh,
                                          const __nv_bfloat16* __restrict__ Wl,
                                          float* __restrict__ C,
                                          __nv_bfloat16* __restrict__ Oh,
                                          __nv_bfloat16* __restrict__ Ol,
                                          const float* __restrict__ bias,
                                          int nrows) {
    constexpr int AEL  = 128 * SA16;          // 3072 elems per A plane
    constexpr int WEL  = 16 * SWS;            // 1152 elems per W plane
    constexpr int BUFE = 2 * AEL + 2 * WEL;   // 8448 elems
    constexpr int BUFB = BUFE * 2;            // 16896 bytes
    constexpr int EPI  = 128 * SE * 4;        // 34816
    constexpr int SBY  = RELU ? (2 * BUFB > EPI ? 2 * BUFB : EPI) : 2 * BUFB;
    __shared__ alignas(256) unsigned char sraw[SBY];
    const uint32_t sb = smem_u32(sraw);

    const int tid  = threadIdx.x;
    const int warp = tid >> 5;
    const int row0 = blockIdx.x * 128;
    const int col0 = blockIdx.y * CTILE;

    constexpr int NT = CTILE / 16;   // 4
    wmma::fragment<wmma::accumulator, 16, 16, 16, float> acc[NT];
    #pragma unroll
    for (int nt = 0; nt < NT; nt++) wmma::fill_fragment(acc[nt], 0.0f);

    auto stage = [&](int buf, int kb) {
        uint32_t base = sb + (uint32_t)buf * BUFB;
        {   // A chunk [128 x 16], hi+lo: one 16B transfer per plane per thread
            int idx = tid * 8;
            int r = idx >> 4, c = idx & 15;
            int grow = row0 + r;
            bool ok = grow < nrows;
            size_t goff = (size_t)grow * 128 + kb + c;
            const void* pa = ok ? (const void*)(Ah + goff) : (const void*)Ah;
            const void* pl = ok ? (const void*)(Al + goff) : (const void*)Al;
            int nb = ok ? 16 : 0;
            uint32_t so = base + (uint32_t)(r * SA16 + c) * 2;
            cp16(so, pa, nb);
            cp16(so + AEL * 2, pl, nb);
        }
        if (tid < 128) {   // W chunk [16 x 64], hi+lo
            int idx = tid * 8;
            int kr = idx >> 6, n = idx & 63;
            size_t go = (size_t)(kb + kr) * OUTC + col0 + n;
            uint32_t so = base + (uint32_t)(2 * AEL + kr * SWS + n) * 2;
            cp16(so, Wh + go, 16);
            cp16(so + WEL * 2, Wl + go, 16);
        }
    };

    stage(0, 0); CP_COMMIT();
    #pragma unroll
    for (int c = 0; c < 8; c++) {
        if (c < 7) { stage((c + 1) & 1, (c + 1) * 16); CP_COMMIT(); CP_WAIT1(); }
        else       { CP_WAIT0(); }
        __syncthreads();

        const __nv_bfloat16* bA = (const __nv_bfloat16*)(sraw + (c & 1) * BUFB);
        const __nv_bfloat16* bW = bA + 2 * AEL;
        wmma::fragment<wmma::matrix_a, 16, 16, 16, __nv_bfloat16, wmma::row_major> fah, fal;
        wmma::load_matrix_sync(fah, bA + warp * 16 * SA16, SA16);
        wmma::load_matrix_sync(fal, bA + AEL + warp * 16 * SA16, SA16);
        #pragma unroll
        for (int nt = 0; nt < NT; nt++) {
            wmma::fragment<wmma::matrix_b, 16, 16, 16, __nv_bfloat16, wmma::row_major> fbh, fbl;
            wmma::load_matrix_sync(fbh, bW + nt * 16, SWS);
            wmma::load_matrix_sync(fbl, bW + WEL + nt * 16, SWS);
            wmma::mma_sync(acc[nt], fah, fbh, acc[nt]);
            wmma::mma_sync(acc[nt], fah, fbl, acc[nt]);
            wmma::mma_sync(acc[nt], fal, fbh, acc[nt]);
        }
        __syncthreads();
    }

    if (RELU) {
        float* sC = (float*)sraw;
        #pragma unroll
        for (int nt = 0; nt < NT; nt++)
            wmma::store_matrix_sync(sC + warp * 16 * SE + nt * 16, acc[nt],
                                    SE, wmma::mem_row_major);
        __syncthreads();
        for (int idx = tid * 4; idx < 128 * CTILE; idx += 1024) {
            int r = idx >> 6, c = idx & 63;
            int grow = row0 + r;
            if (grow < nrows) {
                float4 v = *(float4*)(sC + r * SE + c);
                float4 bv = *(const float4*)(bias + col0 + c);
                v.x = fmaxf(v.x + bv.x, 0.0f);
                v.y = fmaxf(v.y + bv.y, 0.0f);
                v.z = fmaxf(v.z + bv.z, 0.0f);
                v.w = fmaxf(v.w + bv.w, 0.0f);
                uint2 h, l; cvt4(v, h, l);
                *(uint2*)(Oh + (size_t)grow * 128 + col0 + c) = h;
                *(uint2*)(Ol + (size_t)grow * 128 + col0 + c) = l;
            }
        }
    } else {
        int wr = row0 + warp * 16;
        if (wr + 16 <= nrows) {
            #pragma unroll
            for (int nt = 0; nt < NT; nt++)
                wmma::store_matrix_sync(C + (size_t)wr * OUTC + col0 + nt * 16, acc[nt],
                                        OUTC, wmma::mem_row_major);
        }
    }
}

__global__ __launch_bounds__(256) void k_wmma1(const float* __restrict__ b1) {
    wmma_body<128, true>(gAXh, gAXl, gW1h, gW1l, nullptr, gZ1h, gZ1l, b1, N_NODES);
}
__global__ __launch_bounds__(256) void k_wmma2() {
    wmma_body<64, false>(gZ1h, gZ1l, gW2h, gW2l, g_h2, nullptr, nullptr, nullptr, N_NODES);
}

// ---------------- layer-2 aggregation: warp per dst node, 64 feats ----------------
__global__ void k_agg2(const float* __restrict__ b2) {
    int gw = (blockIdx.x * blockDim.x + threadIdx.x) >> 5;
    int lane = threadIdx.x & 31;
    if (gw >= N_NODES) return;
    int d = gw;
    float dv = g_dinv[d];
    float self = dv * dv;

    float2 h = ((const float2*)(g_h2 + (size_t)d * 64))[lane];
    float2 acc = make_float2(h.x * self, h.y * self);

    int e0 = edge_off(d), e1 = edge_off(d + 1);
    int j = e0;
    for (; j + 4 <= e1; j += 4) {
        int s0 = g_esrc[j], s1 = g_esrc[j + 1], s2 = g_esrc[j + 2], s3 = g_esrc[j + 3];
        float n0 = dv * g_dinv[s0];
        float n1 = dv * g_dinv[s1];
        float n2 = dv * g_dinv[s2];
        float n3 = dv * g_dinv[s3];
        float2 v0 = ((const float2*)(g_h2 + (size_t)s0 * 64))[lane];
        float2 v1 = ((const float2*)(g_h2 + (size_t)s1 * 64))[lane];
        float2 v2 = ((const float2*)(g_h2 + (size_t)s2 * 64))[lane];
        float2 v3 = ((const float2*)(g_h2 + (size_t)s3 * 64))[lane];
        acc.x += v0.x * n0 + v1.x * n1 + v2.x * n2 + v3.x * n3;
        acc.y += v0.y * n0 + v1.y * n1 + v2.y * n2 + v3.y * n3;
    }
    for (; j < e1; j++) {
        int s0 = g_esrc[j];
        float n0 = dv * g_dinv[s0];
        float2 v0 = ((const float2*)(g_h2 + (size_t)s0 * 64))[lane];
        acc.x += v0.x * n0; acc.y += v0.y * n0;
    }
    float2 bb = ((const float2*)b2)[lane];
    acc.x += bb.x; acc.y += bb.y;
    ((float2*)(g_z2 + (size_t)d * 64))[lane] = acc;
}

// ---------------- decode: warp per 4 edges; also restores counter zeros ----------------
__global__ void k_decode(const int* __restrict__ pos_ei,
                         const int* __restrict__ neg_ei,
                         float* __restrict__ out) {
    int gtid = blockIdx.x * blockDim.x + threadIdx.x;
    if (gtid < N_NODES) { g_cnt[gtid] = 0; g_cur[gtid] = 0; }   // invariant for next run
    int w = gtid >> 5;
    int lane = gtid & 31;
    int ebase = w * 4;                       // N_EDGES_TOT % 4 == 0 -> no tail
    if (ebase >= N_EDGES_TOT) return;

    float s[4];
    #pragma unroll
    for (int q = 0; q < 4; q++) {
        int e = ebase + q;
        int a, b;
        if (e < N_POS) { a = pos_ei[e]; b = pos_ei[N_POS + e]; }
        else { int f = e - N_POS; a = neg_ei[f]; b = neg_ei[N_POS + f]; }
        float2 u = ((const float2*)(g_z2 + (size_t)a * 64))[lane];
        float2 v = ((const float2*)(g_z2 + (size_t)b * 64))[lane];
        s[q] = u.x * v.x + u.y * v.y;
    }
    #pragma unroll
    for (int o = 16; o > 0; o >>= 1) {
        s[0] += __shfl_xor_sync(0xffffffffu, s[0], o);
        s[1] += __shfl_xor_sync(0xffffffffu, s[1], o);
        s[2] += __shfl_xor_sync(0xffffffffu, s[2], o);
        s[3] += __shfl_xor_sync(0xffffffffu, s[3], o);
    }
    if (lane == 0) {
        out[ebase + 0] = s[0];
        out[ebase + 1] = s[1];
        out[ebase + 2] = s[2];
        out[ebase + 3] = s[3];
    }
}

// ---------------- launch ----------------
extern "C" void kernel_launch(void* const* d_in, const int* in_sizes, int n_in,
                              void* d_out, int out_size) {
    const float* x   = (const float*)d_in[0];
    const int*   pos = (const int*)d_in[1];
    const int*   neg = (const int*)d_in[2];
    const float* W1  = (const float*)d_in[3];
    const float* b1  = (const float*)d_in[4];
    const float* W2  = (const float*)d_in[5];
    const float* b2  = (const float*)d_in[6];
    float* out = (float*)d_out;

    const int T = 256;
    const int GB = (N_NODES + 127) / 128;   // 782 row blocks

    k_prep<<<(N_POS + T - 1) / T, T>>>(pos, W1, W2);                  // 1 (W cvt + hist)
    k_scanA<<<NB, SCAN_B>>>();                                        // 2
    k_scanB<<<1, 256>>>();                                            // 3
    k_fill<<<(N_POS + T - 1) / T, T>>>(pos);                          // 4
    k_aggX<<<(N_NODES * 32 + T - 1) / T, T>>>(x);                     // 5
    k_wmma1<<<dim3(GB, 2), 256>>>(b1);                                // 6
    k_wmma2<<<dim3(GB, 1), 256>>>();                                  // 7
    k_agg2<<<(N_NODES * 32 + T - 1) / T, T>>>(b2);                    // 8
    k_decode<<<((size_t)(N_EDGES_TOT / 4) * 32 + T - 1) / T, T>>>(pos, neg, out); // 9
}

// round 16
// speedup vs baseline: 1.1412x; 1.0089x over previous
#include <cuda_runtime.h>
#include <cuda_bf16.h>
#include <mma.h>
#include <math.h>
#include <stdint.h>

using namespace nvcuda;

#define N_NODES 100000
#define IN_CH   128
#define HIDDEN  128
#define OUT_CH  64
#define N_POS   600000
#define N_EDGES_TOT 1200000

#define SCAN_B 512
#define NB ((N_NODES + SCAN_B - 1) / SCAN_B)   // 196

// ---------------- scratch (no cudaMalloc allowed) ----------------
__device__ float g_h2[(size_t)N_NODES * OUT_CH];   // z1 @ W2
__device__ float g_z2[(size_t)N_NODES * OUT_CH];   // agg2 + b2
__device__ float g_dinv[N_NODES];
__device__ int   g_cnt[N_NODES];     // zeroed by decode (prev run) / module init
__device__ int   g_offs[N_NODES + 1];   // block-LOCAL exclusive prefixes
__device__ int   g_esrc[N_POS];
__device__ int   g_slot[N_POS];         // per-edge slot within its dst bucket
__device__ int   g_bsum[NB];            // exclusive block prefix (after scanA final)
__device__ int   g_tick;                // scanA completion ticket (zeroed by decode)
// bf16 hi/lo planes
__device__ __nv_bfloat16 gAXh[(size_t)N_NODES * 128], gAXl[(size_t)N_NODES * 128]; // agg(x)
__device__ __nv_bfloat16 gZ1h[(size_t)N_NODES * 128], gZ1l[(size_t)N_NODES * 128]; // relu(aggX@W1+b1)
__device__ __nv_bfloat16 gW1h[128 * 128], gW1l[128 * 128];
__device__ __nv_bfloat16 gW2h[128 * 64],  gW2l[128 * 64];

// ---------------- helpers ----------------
__device__ __forceinline__ uint32_t pack2(float a, float b) {
    uint32_t r;
    asm("cvt.rn.satfinite.bf16x2.f32 %0, %1, %2;" : "=r"(r) : "f"(b), "f"(a));
    return r;
}
__device__ __forceinline__ float bf16_round(float v) {
    return __bfloat162float(__float2bfloat16(v));
}
__device__ __forceinline__ void cvt4(float4 v, uint2& h, uint2& l) {
    h = make_uint2(pack2(v.x, v.y), pack2(v.z, v.w));
    l = make_uint2(pack2(v.x - bf16_round(v.x), v.y - bf16_round(v.y)),
                   pack2(v.z - bf16_round(v.z), v.w - bf16_round(v.w)));
}
__device__ __forceinline__ uint32_t smem_u32(const void* p) {
    uint32_t a;
    asm("{ .reg .u64 t; cvta.to.shared.u64 t, %1; cvt.u32.u64 %0, t; }" : "=r"(a) : "l"(p));
    return a;
}
__device__ __forceinline__ void cp16(uint32_t dst, const void* src, int nbytes) {
    asm volatile("cp.async.cg.shared.global [%0], [%1], 16, %2;"
                 :: "r"(dst), "l"(src), "r"(nbytes) : "memory");
}
#define CP_COMMIT() asm volatile("cp.async.commit_group;" ::: "memory")
#define CP_WAIT1()  asm volatile("cp.async.wait_group 1;" ::: "memory")
#define CP_WAIT0()  asm volatile("cp.async.wait_group 0;" ::: "memory")

// ---------------- prep: W cvt + histogram with slot capture ----------------
__global__ void k_prep(const int* __restrict__ pos_ei,
                       const float* __restrict__ W1,
                       const float* __restrict__ W2) {
    int i = blockIdx.x * blockDim.x + threadIdx.x;
    if (i < (128 * 128) / 4) {
        float4 v = ((const float4*)W1)[i];
        uint2 h, l; cvt4(v, h, l);
        ((uint2*)gW1h)[i] = h;
        ((uint2*)gW1l)[i] = l;
    }
    if (i < (128 * 64) / 4) {
        float4 v = ((const float4*)W2)[i];
        uint2 h, l; cvt4(v, h, l);
        ((uint2*)gW2h)[i] = h;
        ((uint2*)gW2l)[i] = l;
    }
    if (i < N_POS) {
        int d = pos_ei[N_POS + i];
        g_slot[i] = atomicAdd(&g_cnt[d], 1);   // unique slot within dst bucket
    }
}

// scanA: block-local exclusive scan + dinv; last-arriving block scans g_bsum.
__global__ __launch_bounds__(SCAN_B) void k_scanA() {
    __shared__ int wsum[16];
    __shared__ int s_ticket;
    int i = blockIdx.x * SCAN_B + threadIdx.x;
    int lane = threadIdx.x & 31, wid = threadIdx.x >> 5;
    int v = (i < N_NODES) ? g_cnt[i] : 0;
    if (i < N_NODES) g_dinv[i] = rsqrtf((float)v + 1.0f);

    int s = v;
    #pragma unroll
    for (int o = 1; o < 32; o <<= 1) {
        int t = __shfl_up_sync(0xffffffffu, s, o);
        if (lane >= o) s += t;
    }
    if (lane == 31) wsum[wid] = s;
    __syncthreads();
    if (wid == 0) {
        int w = (lane < 16) ? wsum[lane] : 0;
        #pragma unroll
        for (int o = 1; o < 16; o <<= 1) {
            int t = __shfl_up_sync(0xffffffffu, w, o);
            if (lane >= o) w += t;
        }
        if (lane < 16) wsum[lane] = w;
    }
    __syncthreads();
    int excl = s - v + (wid > 0 ? wsum[wid - 1] : 0);
    if (i <= N_NODES) g_offs[i] = excl;
    if (threadIdx.x == 0) {
        g_bsum[blockIdx.x] = wsum[15];
        __threadfence();
        s_ticket = atomicAdd(&g_tick, 1);
    }
    __syncthreads();
    if (s_ticket == NB - 1) {
        // final: exclusive scan of NB block sums (NB <= SCAN_B)
        int bv = (threadIdx.x < NB) ? g_bsum[threadIdx.x] : 0;
        int bs = bv;
        #pragma unroll
        for (int o = 1; o < 32; o <<= 1) {
            int t = __shfl_up_sync(0xffffffffu, bs, o);
            if (lane >= o) bs += t;
        }
        __syncthreads();                       // reuse wsum safely
        if (lane == 31) wsum[wid] = bs;
        __syncthreads();
        if (wid == 0) {
            int w = (lane < 16) ? wsum[lane] : 0;
            #pragma unroll
            for (int o = 1; o < 16; o <<= 1) {
                int t = __shfl_up_sync(0xffffffffu, w, o);
                if (lane >= o) w += t;
            }
            if (lane < 16) wsum[lane] = w;
        }
        __syncthreads();
        int bexcl = bs - bv + (wid > 0 ? wsum[wid - 1] : 0);
        if (threadIdx.x < NB) g_bsum[threadIdx.x] = bexcl;
    }
}

__device__ __forceinline__ int edge_off(int i) {
    return g_offs[i] + g_bsum[i >> 9];
}

// fill: atomic-free scatter using pre-captured slots
__global__ void k_fill(const int* __restrict__ pos_ei) {
    int e = blockIdx.x * blockDim.x + threadIdx.x;
    if (e < N_POS) {
        int s = pos_ei[e];
        int d = pos_ei[N_POS + e];
        g_esrc[edge_off(d) + g_slot[e]] = s;
    }
}

// ---------------- layer-1 aggregation on RAW x (agg(x@W)=agg(x)@W) ----
__global__ void k_aggX(const float* __restrict__ x) {
    int gw = (blockIdx.x * blockDim.x + threadIdx.x) >> 5;
    int lane = threadIdx.x & 31;
    if (gw >= N_NODES) return;
    int d = gw;
    float dv = g_dinv[d];
    float self = dv * dv;

    float4 h = ((const float4*)(x + (size_t)d * 128))[lane];
    float4 acc = make_float4(h.x * self, h.y * self, h.z * self, h.w * self);

    int e0 = edge_off(d), e1 = edge_off(d + 1);
    int j = e0;
    for (; j + 4 <= e1; j += 4) {
        int s0 = g_esrc[j], s1 = g_esrc[j + 1], s2 = g_esrc[j + 2], s3 = g_esrc[j + 3];
        float n0 = dv * g_dinv[s0];
        float n1 = dv * g_dinv[s1];
        float n2 = dv * g_dinv[s2];
        float n3 = dv * g_dinv[s3];
        float4 v0 = ((const float4*)(x + (size_t)s0 * 128))[lane];
        float4 v1 = ((const float4*)(x + (size_t)s1 * 128))[lane];
        float4 v2 = ((const float4*)(x + (size_t)s2 * 128))[lane];
        float4 v3 = ((const float4*)(x + (size_t)s3 * 128))[lane];
        acc.x += v0.x * n0 + v1.x * n1 + v2.x * n2 + v3.x * n3;
        acc.y += v0.y * n0 + v1.y * n1 + v2.y * n2 + v3.y * n3;
        acc.z += v0.z * n0 + v1.z * n1 + v2.z * n2 + v3.z * n3;
        acc.w += v0.w * n0 + v1.w * n1 + v2.w * n2 + v3.w * n3;
    }
    for (; j < e1; j++) {
        int s0 = g_esrc[j];
        float n0 = dv * g_dinv[s0];
        float4 v0 = ((const float4*)(x + (size_t)s0 * 128))[lane];
        acc.x += v0.x * n0; acc.y += v0.y * n0;
        acc.z += v0.z * n0; acc.w += v0.w * n0;
    }
    uint2 hh, ll; cvt4(acc, hh, ll);
    ((uint2*)(gAXh + (size_t)d * 128))[lane] = hh;
    ((uint2*)(gAXl + (size_t)d * 128))[lane] = ll;
}

// =================================================================
// WMMA GEMM body: cp.async double-buffered, k-chunk=16, 8 warps x 16 rows.
// =================================================================
#define SA16 24          // A smem stride (elems), chunk k=16
#define CTILE 64         // columns per CTA
#define SWS 72           // W smem stride (elems)
#define SE 68            // epilogue fp32 scratch stride

template <int OUTC, bool RELU>
__device__ __forceinline__ void wmma_body(const __nv_bfloat16* __restrict__ Ah,
                                          const __nv_bfloat16* __restrict__ Al,
                                          const __nv_bfloat16* __restrict__ Wh,
                                          const __nv_bfloat16* __restrict__ Wl,
                                          float* __restrict__ C,
                                          __nv_bfloat16* __restrict__ Oh,
                                          __nv_bfloat16* __restrict__ Ol,
                                          const float* __restrict__ bias,
                                          int nrows) {
    constexpr int AEL  = 128 * SA16;
    constexpr int WEL  = 16 * SWS;
    constexpr int BUFE = 2 * AEL + 2 * WEL;
    constexpr int BUFB = BUFE * 2;
    constexpr int EPI  = 128 * SE * 4;
    constexpr int SBY  = RELU ? (2 * BUFB > EPI ? 2 * BUFB : EPI) : 2 * BUFB;
    __shared__ alignas(256) unsigned char sraw[SBY];
    const uint32_t sb = smem_u32(sraw);

    const int tid  = threadIdx.x;
    const int warp = tid >> 5;
    const int row0 = blockIdx.x * 128;
    const int col0 = blockIdx.y * CTILE;

    constexpr int NT = CTILE / 16;   // 4
    wmma::fragment<wmma::accumulator, 16, 16, 16, float> acc[NT];
    #pragma unroll
    for (int nt = 0; nt < NT; nt++) wmma::fill_fragment(acc[nt], 0.0f);

    auto stage = [&](int buf, int kb) {
        uint32_t base = sb + (uint32_t)buf * BUFB;
        {
            int idx = tid * 8;
            int r = idx >> 4, c = idx & 15;
            int grow = row0 + r;
            bool ok = grow < nrows;
            size_t goff = (size_t)grow * 128 + kb + c;
            const void* pa = ok ? (const void*)(Ah + goff) : (const void*)Ah;
            const void* pl = ok ? (const void*)(Al + goff) : (const void*)Al;
            int nb = ok ? 16 : 0;
            uint32_t so = base + (uint32_t)(r * SA16 + c) * 2;
            cp16(so, pa, nb);
            cp16(so + AEL * 2, pl, nb);
        }
        if (tid < 128) {
            int idx = tid * 8;
            int kr = idx >> 6, n = idx & 63;
            size_t go = (size_t)(kb + kr) * OUTC + col0 + n;
            uint32_t so = base + (uint32_t)(2 * AEL + kr * SWS + n) * 2;
            cp16(so, Wh + go, 16);
            cp16(so + WEL * 2, Wl + go, 16);
        }
    };

    stage(0, 0); CP_COMMIT();
    #pragma unroll
    for (int c = 0; c < 8; c++) {
        if (c < 7) { stage((c + 1) & 1, (c + 1) * 16); CP_COMMIT(); CP_WAIT1(); }
        else       { CP_WAIT0(); }
        __syncthreads();

        const __nv_bfloat16* bA = (const __nv_bfloat16*)(sraw + (c & 1) * BUFB);
        const __nv_bfloat16* bW = bA + 2 * AEL;
        wmma::fragment<wmma::matrix_a, 16, 16, 16, __nv_bfloat16, wmma::row_major> fah, fal;
        wmma::load_matrix_sync(fah, bA + warp * 16 * SA16, SA16);
        wmma::load_matrix_sync(fal, bA + AEL + warp * 16 * SA16, SA16);
        #pragma unroll
        for (int nt = 0; nt < NT; nt++) {
            wmma::fragment<wmma::matrix_b, 16, 16, 16, __nv_bfloat16, wmma::row_major> fbh, fbl;
            wmma::load_matrix_sync(fbh, bW + nt * 16, SWS);
            wmma::load_matrix_sync(fbl, bW + WEL + nt * 16, SWS);
            wmma::mma_sync(acc[nt], fah, fbh, acc[nt]);
            wmma::mma_sync(acc[nt], fah, fbl, acc[nt]);
            wmma::mma_sync(acc[nt], fal, fbh, acc[nt]);
        }
        __syncthreads();
    }

    if (RELU) {
        float* sC = (float*)sraw;
        #pragma unroll
        for (int nt = 0; nt < NT; nt++)
            wmma::store_matrix_sync(sC + warp * 16 * SE + nt * 16, acc[nt],
                                    SE, wmma::mem_row_major);
        __syncthreads();
        for (int idx = tid * 4; idx < 128 * CTILE; idx += 1024) {
            int r = idx >> 6, c = idx & 63;
            int grow = row0 + r;
            if (grow < nrows) {
                float4 v = *(float4*)(sC + r * SE + c);
                float4 bv = *(const float4*)(bias + col0 + c);
                v.x = fmaxf(v.x + bv.x, 0.0f);
                v.y = fmaxf(v.y + bv.y, 0.0f);
                v.z = fmaxf(v.z + bv.z, 0.0f);
                v.w = fmaxf(v.w + bv.w, 0.0f);
                uint2 h, l; cvt4(v, h, l);
                *(uint2*)(Oh + (size_t)grow * 128 + col0 + c) = h;
                *(uint2*)(Ol + (size_t)grow * 128 + col0 + c) = l;
            }
        }
    } else {
        int wr = row0 + warp * 16;
        if (wr + 16 <= nrows) {
            #pragma unroll
            for (int nt = 0; nt < NT; nt++)
                wmma::store_matrix_sync(C + (size_t)wr * OUTC + col0 + nt * 16, acc[nt],
                                        OUTC, wmma::mem_row_major);
        }
    }
}

__global__ __launch_bounds__(256) void k_wmma1(const float* __restrict__ b1) {
    wmma_body<128, true>(gAXh, gAXl, gW1h, gW1l, nullptr, gZ1h, gZ1l, b1, N_NODES);
}
__global__ __launch_bounds__(256) void k_wmma2() {
    wmma_body<64, false>(gZ1h, gZ1l, gW2h, gW2l, g_h2, nullptr, nullptr, nullptr, N_NODES);
}

// ---------------- layer-2 aggregation: warp per dst node, 64 feats ----------------
__global__ void k_agg2(const float* __restrict__ b2) {
    int gw = (blockIdx.x * blockDim.x + threadIdx.x) >> 5;
    int lane = threadIdx.x & 31;
    if (gw >= N_NODES) return;
    int d = gw;
    float dv = g_dinv[d];
    float self = dv * dv;

    float2 h = ((const float2*)(g_h2 + (size_t)d * 64))[lane];
    float2 acc = make_float2(h.x * self, h.y * self);

    int e0 = edge_off(d), e1 = edge_off(d + 1);
    int j = e0;
    for (; j + 4 <= e1; j += 4) {
        int s0 = g_esrc[j], s1 = g_esrc[j + 1], s2 = g_esrc[j + 2], s3 = g_esrc[j + 3];
        float n0 = dv * g_dinv[s0];
        float n1 = dv * g_dinv[s1];
        float n2 = dv * g_dinv[s2];
        float n3 = dv * g_dinv[s3];
        float2 v0 = ((const float2*)(g_h2 + (size_t)s0 * 64))[lane];
        float2 v1 = ((const float2*)(g_h2 + (size_t)s1 * 64))[lane];
        float2 v2 = ((const float2*)(g_h2 + (size_t)s2 * 64))[lane];
        float2 v3 = ((const float2*)(g_h2 + (size_t)s3 * 64))[lane];
        acc.x += v0.x * n0 + v1.x * n1 + v2.x * n2 + v3.x * n3;
        acc.y += v0.y * n0 + v1.y * n1 + v2.y * n2 + v3.y * n3;
    }
    for (; j < e1; j++) {
        int s0 = g_esrc[j];
        float n0 = dv * g_dinv[s0];
        float2 v0 = ((const float2*)(g_h2 + (size_t)s0 * 64))[lane];
        acc.x += v0.x * n0; acc.y += v0.y * n0;
    }
    float2 bb = ((const float2*)b2)[lane];
    acc.x += bb.x; acc.y += bb.y;
    ((float2*)(g_z2 + (size_t)d * 64))[lane] = acc;
}

// ---------------- decode: warp per 4 edges; restores counters for next replay ----
__global__ void k_decode(const int* __restrict__ pos_ei,
                         const int* __restrict__ neg_ei,
                         float* __restrict__ out) {
    int gtid = blockIdx.x * blockDim.x + threadIdx.x;
    if (gtid < N_NODES) g_cnt[gtid] = 0;
    if (gtid == 0) g_tick = 0;
    int w = gtid >> 5;
    int lane = gtid & 31;
    int ebase = w * 4;                       // N_EDGES_TOT % 4 == 0 -> no tail
    if (ebase >= N_EDGES_TOT) return;

    float s[4];
    #pragma unroll
    for (int q = 0; q < 4; q++) {
        int e = ebase + q;
        int a, b;
        if (e < N_POS) { a = pos_ei[e]; b = pos_ei[N_POS + e]; }
        else { int f = e - N_POS; a = neg_ei[f]; b = neg_ei[N_POS + f]; }
        float2 u = ((const float2*)(g_z2 + (size_t)a * 64))[lane];
        float2 v = ((const float2*)(g_z2 + (size_t)b * 64))[lane];
        s[q] = u.x * v.x + u.y * v.y;
    }
    #pragma unroll
    for (int o = 16; o > 0; o >>= 1) {
        s[0] += __shfl_xor_sync(0xffffffffu, s[0], o);
        s[1] += __shfl_xor_sync(0xffffffffu, s[1], o);
        s[2] += __shfl_xor_sync(0xffffffffu, s[2], o);
        s[3] += __shfl_xor_sync(0xffffffffu, s[3], o);
    }
    if (lane == 0) {
        out[ebase + 0] = s[0];
        out[ebase + 1] = s[1];
        out[ebase + 2] = s[2];
        out[ebase + 3] = s[3];
    }
}

// ---------------- launch ----------------
extern "C" void kernel_launch(void* const* d_in, const int* in_sizes, int n_in,
                              void* d_out, int out_size) {
    const float* x   = (const float*)d_in[0];
    const int*   pos = (const int*)d_in[1];
    const int*   neg = (const int*)d_in[2];
    const float* W1  = (const float*)d_in[3];
    const float* b1  = (const float*)d_in[4];
    const float* W2  = (const float*)d_in[5];
    const float* b2  = (const float*)d_in[6];
    float* out = (float*)d_out;

    const int T = 256;
    const int GB = (N_NODES + 127) / 128;   // 782 row blocks

    k_prep<<<(N_POS + T - 1) / T, T>>>(pos, W1, W2);                  // 1
    k_scanA<<<NB, SCAN_B>>>();                                        // 2 (+ final bsum scan)
    k_fill<<<(N_POS + T - 1) / T, T>>>(pos);                          // 3 (atomic-free)
    k_aggX<<<(N_NODES * 32 + T - 1) / T, T>>>(x);                     // 4  <- profiled
    k_wmma1<<<dim3(GB, 2), 256>>>(b1);                                // 5
    k_wmma2<<<dim3(GB, 1), 256>>>();                                  // 6
    k_agg2<<<(N_NODES * 32 + T - 1) / T, T>>>(b2);                    // 7
    k_decode<<<((size_t)(N_EDGES_TOT / 4) * 32 + T - 1) / T, T>>>(pos, neg, out); // 8
}